// round 1
// baseline (speedup 1.0000x reference)
#include <cuda_runtime.h>
#include <math.h>

#define B 2
#define T 2048
#define V 32000
#define D 1024
#define DF 4096
#define L 6
#define BT (B*T)

// ---------------- scratch (device globals; no allocation allowed) ----------
__device__ float g_x[BT * D];                 // 16 MB
__device__ float g_q[BT * D];                 // 16 MB
__device__ float g_k[BT * D];                 // 16 MB
__device__ float g_v[BT * D];                 // 16 MB
__device__ float g_attn[BT * D];              // 16 MB (attn out / ffn out)
__device__ float g_scores[(size_t)B * T * T]; // 32 MB
__device__ float g_h[BT * DF];                // 64 MB

// ---------------- reduction helpers ----------------------------------------
__device__ __forceinline__ float block_sum(float v, float* red) {
    int tid = threadIdx.x, lane = tid & 31, warp = tid >> 5;
    int nw = blockDim.x >> 5;
    #pragma unroll
    for (int o = 16; o; o >>= 1) v += __shfl_xor_sync(0xffffffffu, v, o);
    if (lane == 0) red[warp] = v;
    __syncthreads();
    float r = (tid < nw) ? red[tid] : 0.0f;
    if (warp == 0) {
        #pragma unroll
        for (int o = 16; o; o >>= 1) r += __shfl_xor_sync(0xffffffffu, r, o);
        if (tid == 0) red[0] = r;
    }
    __syncthreads();
    float out = red[0];
    __syncthreads();
    return out;
}

__device__ __forceinline__ float block_max(float v, float* red) {
    int tid = threadIdx.x, lane = tid & 31, warp = tid >> 5;
    int nw = blockDim.x >> 5;
    #pragma unroll
    for (int o = 16; o; o >>= 1) v = fmaxf(v, __shfl_xor_sync(0xffffffffu, v, o));
    if (lane == 0) red[warp] = v;
    __syncthreads();
    float r = (tid < nw) ? red[tid] : -INFINITY;
    if (warp == 0) {
        #pragma unroll
        for (int o = 16; o; o >>= 1) r = fmaxf(r, __shfl_xor_sync(0xffffffffu, r, o));
        if (tid == 0) red[0] = r;
    }
    __syncthreads();
    float out = red[0];
    __syncthreads();
    return out;
}

// ---------------- embed + positional encoding -------------------------------
__global__ void embed_pe_kernel(const int* __restrict__ tokens,
                                const float* __restrict__ embed,
                                float* __restrict__ x) {
    const int row = blockIdx.x;          // 0..BT-1
    const int t = row % T;
    const int tok = tokens[row];
    const float* erow = embed + (size_t)tok * D;
    float* xrow = x + (size_t)row * D;
    for (int i = threadIdx.x; i < D; i += blockDim.x) {
        int ip = i & ~1;
        // accurate PE via double
        double freq = exp(((double)ip / (double)D) * log(10000.0));
        double angle = (double)t / freq;
        float pe = (i & 1) ? (float)cos(angle) : (float)sin(angle);
        xrow[i] = erow[i] + pe;
    }
}

// ---------------- classic 128x128x8 sgemm ----------------------------------
// C = A @ B (+bias) (+relu).  A: [M,K] row-major. B: [K,N] (TRANSB=false) or
// [N,K] (TRANSB=true), row-major.  All of M%128, N%128, K%8 (and %4 for the
// float4 loads) must hold — true for every shape in this model.
// blockIdx.z batches with the given element strides.
template<bool TRANSB, bool RELU, bool BIAS>
__global__ __launch_bounds__(256) void sgemm_kernel(
    const float* __restrict__ A, const float* __restrict__ Bm,
    const float* __restrict__ bias, float* __restrict__ C,
    int M, int N, int K, long strideA, long strideB, long strideC)
{
    const int BM = 128, BN = 128, BK = 8;
    __shared__ float As[BK][BM];
    __shared__ float Bs[BK][BN];

    const long bz = blockIdx.z;
    A  += bz * strideA;
    Bm += bz * strideB;
    C  += bz * strideC;

    const int bm = blockIdx.y * BM;
    const int bn = blockIdx.x * BN;
    const int tid = threadIdx.x;             // 256 threads

    // A-tile (and TRANSB B-tile) load mapping: 128 rows x 2 float4
    const int arow  = tid >> 1;
    const int acol4 = (tid & 1) * 4;
    // NN B-tile load mapping: 8 rows x 32 float4
    const int brow  = tid >> 5;
    const int bcol4 = (tid & 31) * 4;
    // compute mapping: 16x16 threads, each 8x8
    const int tm = (tid >> 4) * 8;
    const int tn = (tid & 15) * 8;

    float acc[8][8];
    #pragma unroll
    for (int i = 0; i < 8; i++)
        #pragma unroll
        for (int j = 0; j < 8; j++) acc[i][j] = 0.0f;

    for (int k0 = 0; k0 < K; k0 += BK) {
        float4 a4 = *(const float4*)(A + (long)(bm + arow) * K + k0 + acol4);
        As[acol4 + 0][arow] = a4.x;
        As[acol4 + 1][arow] = a4.y;
        As[acol4 + 2][arow] = a4.z;
        As[acol4 + 3][arow] = a4.w;
        if (!TRANSB) {
            float4 b4 = *(const float4*)(Bm + (long)(k0 + brow) * N + bn + bcol4);
            *(float4*)&Bs[brow][bcol4] = b4;
        } else {
            float4 b4 = *(const float4*)(Bm + (long)(bn + arow) * K + k0 + acol4);
            Bs[acol4 + 0][arow] = b4.x;
            Bs[acol4 + 1][arow] = b4.y;
            Bs[acol4 + 2][arow] = b4.z;
            Bs[acol4 + 3][arow] = b4.w;
        }
        __syncthreads();
        #pragma unroll
        for (int kk = 0; kk < BK; ++kk) {
            float af[8], bf[8];
            *(float4*)&af[0] = *(const float4*)&As[kk][tm];
            *(float4*)&af[4] = *(const float4*)&As[kk][tm + 4];
            *(float4*)&bf[0] = *(const float4*)&Bs[kk][tn];
            *(float4*)&bf[4] = *(const float4*)&Bs[kk][tn + 4];
            #pragma unroll
            for (int i = 0; i < 8; i++)
                #pragma unroll
                for (int j = 0; j < 8; j++)
                    acc[i][j] += af[i] * bf[j];
        }
        __syncthreads();
    }

    #pragma unroll
    for (int i = 0; i < 8; i++) {
        const long row = bm + tm + i;
        #pragma unroll
        for (int j = 0; j < 8; j += 4) {
            float4 o;
            o.x = acc[i][j + 0];
            o.y = acc[i][j + 1];
            o.z = acc[i][j + 2];
            o.w = acc[i][j + 3];
            if (BIAS) {
                const float* bp = bias + bn + tn + j;
                o.x += bp[0]; o.y += bp[1]; o.z += bp[2]; o.w += bp[3];
            }
            if (RELU) {
                o.x = fmaxf(o.x, 0.0f); o.y = fmaxf(o.y, 0.0f);
                o.z = fmaxf(o.z, 0.0f); o.w = fmaxf(o.w, 0.0f);
            }
            *(float4*)(C + row * N + bn + tn + j) = o;
        }
    }
}

// ---------------- causal softmax over scores (in place) --------------------
// probs[t,s] = softmax_s<=t(scores[t,s]/32); probs[t,s>t] = 0
__global__ void softmax_causal_kernel(float* __restrict__ scores) {
    const int t = blockIdx.x;
    const int b = blockIdx.y;
    float* row = scores + ((size_t)b * T + t) * T;
    const int n = t + 1;
    const float inv_scale = 0.03125f;  // 1/sqrt(1024)
    __shared__ float red[32];
    const int tid = threadIdx.x;

    float m = -INFINITY;
    for (int s = tid; s < n; s += blockDim.x) m = fmaxf(m, row[s] * inv_scale);
    m = block_max(m, red);

    float sum = 0.0f;
    for (int s = tid; s < n; s += blockDim.x) {
        float e = expf(row[s] * inv_scale - m);
        row[s] = e;
        sum += e;
    }
    sum = block_sum(sum, red);
    const float inv = 1.0f / sum;

    for (int s = tid; s < n; s += blockDim.x) row[s] *= inv;
    for (int s = n + tid; s < T; s += blockDim.x) row[s] = 0.0f;
}

// ---------------- x = LayerNorm(x + y) * g + beta ---------------------------
__global__ void add_ln_kernel(float* __restrict__ x, const float* __restrict__ y,
                              const float* __restrict__ g, const float* __restrict__ beta) {
    const int row = blockIdx.x;
    __shared__ float buf[D];
    __shared__ float red[32];
    float* xr = x + (size_t)row * D;
    const float* yr = y + (size_t)row * D;
    const int tid = threadIdx.x;

    float sum = 0.0f;
    for (int i = tid; i < D; i += blockDim.x) {
        float v = xr[i] + yr[i];
        buf[i] = v;
        sum += v;
    }
    __syncthreads();
    sum = block_sum(sum, red);
    const float mu = sum * (1.0f / D);

    float vs = 0.0f;
    for (int i = tid; i < D; i += blockDim.x) {
        float d = buf[i] - mu;
        vs += d * d;
    }
    vs = block_sum(vs, red);
    const float rstd = rsqrtf(vs * (1.0f / D) + 1e-5f);

    for (int i = tid; i < D; i += blockDim.x)
        xr[i] = (buf[i] - mu) * rstd * g[i] + beta[i];
}

// ---------------- in-place log_softmax over vocab ---------------------------
__global__ void log_softmax_kernel(float* __restrict__ out) {
    float* row = out + (size_t)blockIdx.x * V;
    __shared__ float red[32];
    const int tid = threadIdx.x;

    float m = -INFINITY;
    for (int i = tid; i < V; i += blockDim.x) m = fmaxf(m, row[i]);
    m = block_max(m, red);

    float sum = 0.0f;
    for (int i = tid; i < V; i += blockDim.x) sum += expf(row[i] - m);
    sum = block_sum(sum, red);
    const float lse = m + logf(sum);

    for (int i = tid; i < V; i += blockDim.x) row[i] -= lse;
}

// ---------------- launch ----------------------------------------------------
extern "C" void kernel_launch(void* const* d_in, const int* in_sizes, int n_in,
                              void* d_out, int out_size) {
    const int*   tokens = (const int*)  d_in[0];
    const float* embed  = (const float*)d_in[1];
    const float* Wq     = (const float*)d_in[2];
    const float* bq     = (const float*)d_in[3];
    const float* Wk     = (const float*)d_in[4];
    const float* bk     = (const float*)d_in[5];
    const float* Wv     = (const float*)d_in[6];
    const float* bv     = (const float*)d_in[7];
    const float* g1     = (const float*)d_in[8];
    const float* beta1  = (const float*)d_in[9];
    const float* W1     = (const float*)d_in[10];
    const float* bf1    = (const float*)d_in[11];
    const float* W2     = (const float*)d_in[12];
    const float* bf2    = (const float*)d_in[13];
    const float* g2     = (const float*)d_in[14];
    const float* beta2  = (const float*)d_in[15];
    const float* Wout   = (const float*)d_in[16];
    const float* bout   = (const float*)d_in[17];
    float* out = (float*)d_out;

    float *x, *q, *k, *v, *attn, *scores, *h;
    cudaGetSymbolAddress((void**)&x,      g_x);
    cudaGetSymbolAddress((void**)&q,      g_q);
    cudaGetSymbolAddress((void**)&k,      g_k);
    cudaGetSymbolAddress((void**)&v,      g_v);
    cudaGetSymbolAddress((void**)&attn,   g_attn);
    cudaGetSymbolAddress((void**)&scores, g_scores);
    cudaGetSymbolAddress((void**)&h,      g_h);

    embed_pe_kernel<<<BT, 256>>>(tokens, embed, x);

    for (int l = 0; l < L; ++l) {
        const float* wq = Wq + (size_t)l * D * D;
        const float* wk = Wk + (size_t)l * D * D;
        const float* wv = Wv + (size_t)l * D * D;

        // q/k/v projections: [BT,D] @ [D,D] + bias
        sgemm_kernel<false, false, true><<<dim3(D / 128, BT / 128, 1), 256>>>(
            x, wq, bq + (size_t)l * D, q, BT, D, D, 0, 0, 0);
        sgemm_kernel<false, false, true><<<dim3(D / 128, BT / 128, 1), 256>>>(
            x, wk, bk + (size_t)l * D, k, BT, D, D, 0, 0, 0);
        sgemm_kernel<false, false, true><<<dim3(D / 128, BT / 128, 1), 256>>>(
            x, wv, bv + (size_t)l * D, v, BT, D, D, 0, 0, 0);

        // scores = q @ k^T  per batch
        sgemm_kernel<true, false, false><<<dim3(T / 128, T / 128, B), 256>>>(
            q, k, nullptr, scores, T, T, D,
            (long)T * D, (long)T * D, (long)T * T);

        softmax_causal_kernel<<<dim3(T, B, 1), 256>>>(scores);

        // attn = probs @ v  per batch
        sgemm_kernel<false, false, false><<<dim3(D / 128, T / 128, B), 256>>>(
            scores, v, nullptr, attn, T, D, T,
            (long)T * T, (long)T * D, (long)T * D);

        add_ln_kernel<<<BT, 256>>>(x, attn, g1 + (size_t)l * D, beta1 + (size_t)l * D);

        // FFN
        sgemm_kernel<false, true, true><<<dim3(DF / 128, BT / 128, 1), 256>>>(
            x, W1 + (size_t)l * D * DF, bf1 + (size_t)l * DF, h, BT, DF, D, 0, 0, 0);
        sgemm_kernel<false, false, true><<<dim3(D / 128, BT / 128, 1), 256>>>(
            h, W2 + (size_t)l * DF * D, bf2 + (size_t)l * D, attn, BT, D, DF, 0, 0, 0);

        add_ln_kernel<<<BT, 256>>>(x, attn, g2 + (size_t)l * D, beta2 + (size_t)l * D);
    }

    // logits = x @ Wout + bout, written straight into d_out, then in-place log_softmax
    sgemm_kernel<false, false, true><<<dim3(V / 128, BT / 128, 1), 256>>>(
        x, Wout, bout, out, BT, V, D, 0, 0, 0);
    log_softmax_kernel<<<BT, 256>>>(out);
}

// round 2
// speedup vs baseline: 3.2235x; 3.2235x over previous
#include <cuda_runtime.h>
#include <math.h>
#include <stdint.h>

#define B 2
#define T 2048
#define V 32000
#define D 1024
#define DF 4096
#define L 6
#define BT (B*T)

// ---------------- scratch (device globals; no allocation allowed) ----------
__device__ float g_x[BT * D];                 // 16 MB
__device__ float g_q[BT * D];                 // 16 MB
__device__ float g_k[BT * D];                 // 16 MB
__device__ float g_v[BT * D];                 // 16 MB
__device__ float g_attn[BT * D];              // 16 MB
__device__ float g_scores[(size_t)B * T * T]; // 32 MB
__device__ float g_h[BT * DF];                // 64 MB

// ---------------- helpers ---------------------------------------------------
__device__ __forceinline__ float tf32r(float x) {
    uint32_t u;
    asm("cvt.rna.tf32.f32 %0, %1;" : "=r"(u) : "f"(x));
    return __uint_as_float(u);
}

__device__ __forceinline__ float block_sum(float v, float* red) {
    int tid = threadIdx.x, lane = tid & 31, warp = tid >> 5;
    int nw = blockDim.x >> 5;
    #pragma unroll
    for (int o = 16; o; o >>= 1) v += __shfl_xor_sync(0xffffffffu, v, o);
    if (lane == 0) red[warp] = v;
    __syncthreads();
    float r = (tid < nw) ? red[tid] : 0.0f;
    if (warp == 0) {
        #pragma unroll
        for (int o = 16; o; o >>= 1) r += __shfl_xor_sync(0xffffffffu, r, o);
        if (tid == 0) red[0] = r;
    }
    __syncthreads();
    float out = red[0];
    __syncthreads();
    return out;
}

__device__ __forceinline__ float block_max(float v, float* red) {
    int tid = threadIdx.x, lane = tid & 31, warp = tid >> 5;
    int nw = blockDim.x >> 5;
    #pragma unroll
    for (int o = 16; o; o >>= 1) v = fmaxf(v, __shfl_xor_sync(0xffffffffu, v, o));
    if (lane == 0) red[warp] = v;
    __syncthreads();
    float r = (tid < nw) ? red[tid] : -INFINITY;
    if (warp == 0) {
        #pragma unroll
        for (int o = 16; o; o >>= 1) r = fmaxf(r, __shfl_xor_sync(0xffffffffu, r, o));
        if (tid == 0) red[0] = r;
    }
    __syncthreads();
    float out = red[0];
    __syncthreads();
    return out;
}

// ---------------- embed + positional encoding -------------------------------
__global__ void embed_pe_kernel(const int* __restrict__ tokens,
                                const float* __restrict__ embed,
                                float* __restrict__ x) {
    const int row = blockIdx.x;
    const int t = row % T;
    const int tok = tokens[row];
    const float* erow = embed + (size_t)tok * D;
    float* xrow = x + (size_t)row * D;
    for (int i = threadIdx.x; i < D; i += blockDim.x) {
        int ip = i & ~1;
        double freq = exp(((double)ip / (double)D) * log(10000.0));
        double angle = (double)t / freq;
        float pe = (i & 1) ? (float)cos(angle) : (float)sin(angle);
        xrow[i] = erow[i] + pe;
    }
}

// ---------------- TF32 tensor-core GEMM -------------------------------------
// C = A @ B (+bias)(+relu). A:[M,K] row-major. B:[K,N] (NN) or [N,K] (TT).
// 128x128 block tile, BK=16, 8 warps, warp tile 32x64 (2x8 m16n8k8).
// CAUSAL: 0 = none, 1 = skip tiles fully above diagonal (scores),
//         2 = K-loop truncated at bm+128 (probs @ V).
template<bool TRANSB, bool RELU, bool BIAS, int CAUSAL>
__global__ __launch_bounds__(256) void gemm_tc(
    const float* __restrict__ A, const float* __restrict__ Bm,
    const float* __restrict__ bias, float* __restrict__ C,
    int M, int N, int K, long sA, long sB, long sC)
{
    constexpr int BM = 128, BN = 128, BK = 16;
    constexpr int AST = 20;                  // As row stride (floats), padded
    constexpr int BST = TRANSB ? 20 : 136;   // Bs stride
    constexpr int BSZ = TRANSB ? BM * 20 : BK * 136;

    __shared__ float As[2][BM * AST];
    __shared__ float Bs[2][BSZ];

    const int bm = blockIdx.y * BM;
    const int bn = blockIdx.x * BN;
    if (CAUSAL == 1 && bn > bm + BM - 1) return;   // fully masked tile

    const long bz = blockIdx.z;
    A  += bz * sA;
    Bm += bz * sB;
    C  += bz * sC;

    const int tid  = threadIdx.x;
    const int warp = tid >> 5, lane = tid & 31;
    const int g = lane >> 2, cg = lane & 3;
    const int wm = (warp >> 1) * 32, wn = (warp & 1) * 64;

    const int Kend = (CAUSAL == 2) ? min(K, bm + BM) : K;

    float4 ra[2], rb[2];

    auto ldg = [&](int k0) {
        #pragma unroll
        for (int i = 0; i < 2; i++) {
            int f4 = tid + i * 256;
            ra[i] = *(const float4*)(A + (long)(bm + (f4 >> 2)) * K + k0 + (f4 & 3) * 4);
            if (TRANSB)
                rb[i] = *(const float4*)(Bm + (long)(bn + (f4 >> 2)) * K + k0 + (f4 & 3) * 4);
            else
                rb[i] = *(const float4*)(Bm + (long)(k0 + (f4 >> 5)) * N + bn + (f4 & 31) * 4);
        }
    };

    auto sts = [&](int buf) {
        #pragma unroll
        for (int i = 0; i < 2; i++) {
            int f4 = tid + i * 256;
            int r = f4 >> 2, c4 = (f4 & 3) * 4;
            float* p = &As[buf][r * AST + c4];
            p[0] = tf32r(ra[i].x); p[1] = tf32r(ra[i].y);
            p[2] = tf32r(ra[i].z); p[3] = tf32r(ra[i].w);
            if (TRANSB) {
                float* q = &Bs[buf][r * BST + c4];
                q[0] = tf32r(rb[i].x); q[1] = tf32r(rb[i].y);
                q[2] = tf32r(rb[i].z); q[3] = tf32r(rb[i].w);
            } else {
                int rr = f4 >> 5, cc = (f4 & 31) * 4;
                float* q = &Bs[buf][rr * BST + cc];
                q[0] = tf32r(rb[i].x); q[1] = tf32r(rb[i].y);
                q[2] = tf32r(rb[i].z); q[3] = tf32r(rb[i].w);
            }
        }
    };

    float acc[2][8][4];
    #pragma unroll
    for (int mi = 0; mi < 2; mi++)
        #pragma unroll
        for (int ni = 0; ni < 8; ni++)
            #pragma unroll
            for (int j = 0; j < 4; j++) acc[mi][ni][j] = 0.0f;

    auto comp = [&](int buf) {
        #pragma unroll
        for (int ks = 0; ks < 2; ks++) {
            const int kk = ks * 8 + cg;
            uint32_t af[2][4];
            #pragma unroll
            for (int mi = 0; mi < 2; mi++) {
                int r = wm + mi * 16 + g;
                af[mi][0] = __float_as_uint(As[buf][r * AST + kk]);
                af[mi][1] = __float_as_uint(As[buf][(r + 8) * AST + kk]);
                af[mi][2] = __float_as_uint(As[buf][r * AST + kk + 4]);
                af[mi][3] = __float_as_uint(As[buf][(r + 8) * AST + kk + 4]);
            }
            uint32_t bf[8][2];
            #pragma unroll
            for (int ni = 0; ni < 8; ni++) {
                int col = wn + ni * 8 + g;
                if (TRANSB) {
                    bf[ni][0] = __float_as_uint(Bs[buf][col * BST + kk]);
                    bf[ni][1] = __float_as_uint(Bs[buf][col * BST + kk + 4]);
                } else {
                    bf[ni][0] = __float_as_uint(Bs[buf][kk * BST + col]);
                    bf[ni][1] = __float_as_uint(Bs[buf][(kk + 4) * BST + col]);
                }
            }
            #pragma unroll
            for (int mi = 0; mi < 2; mi++)
                #pragma unroll
                for (int ni = 0; ni < 8; ni++)
                    asm volatile(
                        "mma.sync.aligned.m16n8k8.row.col.f32.tf32.tf32.f32 "
                        "{%0,%1,%2,%3}, {%4,%5,%6,%7}, {%8,%9}, {%0,%1,%2,%3};"
                        : "+f"(acc[mi][ni][0]), "+f"(acc[mi][ni][1]),
                          "+f"(acc[mi][ni][2]), "+f"(acc[mi][ni][3])
                        : "r"(af[mi][0]), "r"(af[mi][1]), "r"(af[mi][2]), "r"(af[mi][3]),
                          "r"(bf[ni][0]), "r"(bf[ni][1]));
        }
    };

    ldg(0);
    sts(0);
    __syncthreads();
    int buf = 0;
    for (int k0 = BK; k0 < Kend; k0 += BK) {
        ldg(k0);
        comp(buf);
        sts(buf ^ 1);
        __syncthreads();
        buf ^= 1;
    }
    comp(buf);

    // epilogue
    #pragma unroll
    for (int mi = 0; mi < 2; mi++) {
        const long r0 = bm + wm + mi * 16 + g;
        #pragma unroll
        for (int ni = 0; ni < 8; ni++) {
            const int col = bn + wn + ni * 8 + cg * 2;
            float b0 = 0.0f, b1 = 0.0f;
            if (BIAS) { b0 = bias[col]; b1 = bias[col + 1]; }
            float2 v0 = make_float2(acc[mi][ni][0] + b0, acc[mi][ni][1] + b1);
            float2 v1 = make_float2(acc[mi][ni][2] + b0, acc[mi][ni][3] + b1);
            if (RELU) {
                v0.x = fmaxf(v0.x, 0.0f); v0.y = fmaxf(v0.y, 0.0f);
                v1.x = fmaxf(v1.x, 0.0f); v1.y = fmaxf(v1.y, 0.0f);
            }
            *(float2*)(C + r0 * N + col) = v0;
            *(float2*)(C + (r0 + 8) * N + col) = v1;
        }
    }
}

// ---------------- causal softmax over scores (in place) --------------------
__global__ void softmax_causal_kernel(float* __restrict__ scores) {
    const int t = blockIdx.x;
    const int b = blockIdx.y;
    float* row = scores + ((size_t)b * T + t) * T;
    const int n = t + 1;
    const float inv_scale = 0.03125f;  // 1/sqrt(1024)
    __shared__ float red[32];
    const int tid = threadIdx.x;

    float m = -INFINITY;
    for (int s = tid; s < n; s += blockDim.x) m = fmaxf(m, row[s] * inv_scale);
    m = block_max(m, red);

    float sum = 0.0f;
    for (int s = tid; s < n; s += blockDim.x) {
        float e = expf(row[s] * inv_scale - m);
        row[s] = e;
        sum += e;
    }
    sum = block_sum(sum, red);
    const float inv = 1.0f / sum;

    for (int s = tid; s < n; s += blockDim.x) row[s] *= inv;
    for (int s = n + tid; s < T; s += blockDim.x) row[s] = 0.0f;
}

// ---------------- x = LayerNorm(x + y) * g + beta ---------------------------
__global__ void add_ln_kernel(float* __restrict__ x, const float* __restrict__ y,
                              const float* __restrict__ g, const float* __restrict__ beta) {
    const int row = blockIdx.x;
    __shared__ float buf[D];
    __shared__ float red[32];
    float* xr = x + (size_t)row * D;
    const float* yr = y + (size_t)row * D;
    const int tid = threadIdx.x;

    float sum = 0.0f;
    for (int i = tid; i < D; i += blockDim.x) {
        float v = xr[i] + yr[i];
        buf[i] = v;
        sum += v;
    }
    __syncthreads();
    sum = block_sum(sum, red);
    const float mu = sum * (1.0f / D);

    float vs = 0.0f;
    for (int i = tid; i < D; i += blockDim.x) {
        float d = buf[i] - mu;
        vs += d * d;
    }
    vs = block_sum(vs, red);
    const float rstd = rsqrtf(vs * (1.0f / D) + 1e-5f);

    for (int i = tid; i < D; i += blockDim.x)
        xr[i] = (buf[i] - mu) * rstd * g[i] + beta[i];
}

// ---------------- in-place log_softmax over vocab ---------------------------
__global__ void log_softmax_kernel(float* __restrict__ out) {
    float* row = out + (size_t)blockIdx.x * V;
    __shared__ float red[32];
    const int tid = threadIdx.x;

    float m = -INFINITY;
    for (int i = tid; i < V; i += blockDim.x) m = fmaxf(m, row[i]);
    m = block_max(m, red);

    float sum = 0.0f;
    for (int i = tid; i < V; i += blockDim.x) sum += expf(row[i] - m);
    sum = block_sum(sum, red);
    const float lse = m + logf(sum);

    for (int i = tid; i < V; i += blockDim.x) row[i] -= lse;
}

// ---------------- launch ----------------------------------------------------
extern "C" void kernel_launch(void* const* d_in, const int* in_sizes, int n_in,
                              void* d_out, int out_size) {
    const int*   tokens = (const int*)  d_in[0];
    const float* embed  = (const float*)d_in[1];
    const float* Wq     = (const float*)d_in[2];
    const float* bq     = (const float*)d_in[3];
    const float* Wk     = (const float*)d_in[4];
    const float* bk     = (const float*)d_in[5];
    const float* Wv     = (const float*)d_in[6];
    const float* bv     = (const float*)d_in[7];
    const float* g1     = (const float*)d_in[8];
    const float* beta1  = (const float*)d_in[9];
    const float* W1     = (const float*)d_in[10];
    const float* bf1    = (const float*)d_in[11];
    const float* W2     = (const float*)d_in[12];
    const float* bf2    = (const float*)d_in[13];
    const float* g2     = (const float*)d_in[14];
    const float* beta2  = (const float*)d_in[15];
    const float* Wout   = (const float*)d_in[16];
    const float* bout   = (const float*)d_in[17];
    float* out = (float*)d_out;

    float *x, *q, *k, *v, *attn, *scores, *h;
    cudaGetSymbolAddress((void**)&x,      g_x);
    cudaGetSymbolAddress((void**)&q,      g_q);
    cudaGetSymbolAddress((void**)&k,      g_k);
    cudaGetSymbolAddress((void**)&v,      g_v);
    cudaGetSymbolAddress((void**)&attn,   g_attn);
    cudaGetSymbolAddress((void**)&scores, g_scores);
    cudaGetSymbolAddress((void**)&h,      g_h);

    embed_pe_kernel<<<BT, 256>>>(tokens, embed, x);

    for (int l = 0; l < L; ++l) {
        const float* wq = Wq + (size_t)l * D * D;
        const float* wk = Wk + (size_t)l * D * D;
        const float* wv = Wv + (size_t)l * D * D;

        gemm_tc<false, false, true, 0><<<dim3(D / 128, BT / 128, 1), 256>>>(
            x, wq, bq + (size_t)l * D, q, BT, D, D, 0, 0, 0);
        gemm_tc<false, false, true, 0><<<dim3(D / 128, BT / 128, 1), 256>>>(
            x, wk, bk + (size_t)l * D, k, BT, D, D, 0, 0, 0);
        gemm_tc<false, false, true, 0><<<dim3(D / 128, BT / 128, 1), 256>>>(
            x, wv, bv + (size_t)l * D, v, BT, D, D, 0, 0, 0);

        // scores = q @ k^T per batch (skip tiles above the diagonal)
        gemm_tc<true, false, false, 1><<<dim3(T / 128, T / 128, B), 256>>>(
            q, k, nullptr, scores, T, T, D,
            (long)T * D, (long)T * D, (long)T * T);

        softmax_causal_kernel<<<dim3(T, B, 1), 256>>>(scores);

        // attn = probs @ v per batch (K truncated at bm+128)
        gemm_tc<false, false, false, 2><<<dim3(D / 128, T / 128, B), 256>>>(
            scores, v, nullptr, attn, T, D, T,
            (long)T * T, (long)T * D, (long)T * D);

        add_ln_kernel<<<BT, 256>>>(x, attn, g1 + (size_t)l * D, beta1 + (size_t)l * D);

        gemm_tc<false, true, true, 0><<<dim3(DF / 128, BT / 128, 1), 256>>>(
            x, W1 + (size_t)l * D * DF, bf1 + (size_t)l * DF, h, BT, DF, D, 0, 0, 0);
        gemm_tc<false, false, true, 0><<<dim3(D / 128, BT / 128, 1), 256>>>(
            h, W2 + (size_t)l * DF * D, bf2 + (size_t)l * D, attn, BT, D, DF, 0, 0, 0);

        add_ln_kernel<<<BT, 256>>>(x, attn, g2 + (size_t)l * D, beta2 + (size_t)l * D);
    }

    gemm_tc<false, false, true, 0><<<dim3(V / 128, BT / 128, 1), 256>>>(
        x, Wout, bout, out, BT, V, D, 0, 0, 0);
    log_softmax_kernel<<<BT, 256>>>(out);
}

// round 3
// speedup vs baseline: 3.3337x; 1.0342x over previous
#include <cuda_runtime.h>
#include <math.h>
#include <stdint.h>

#define B 2
#define T 2048
#define V 32000
#define D 1024
#define DF 4096
#define L 6
#define BT (B*T)

// ---------------- scratch (device globals; no allocation allowed) ----------
__device__ float g_x[BT * D];
__device__ float g_q[BT * D];
__device__ float g_k[BT * D];
__device__ float g_v[BT * D];
__device__ float g_attn[BT * D];
__device__ float g_scores[(size_t)B * T * T];
__device__ float g_h[BT * DF];

// ---------------- helpers ---------------------------------------------------
__device__ __forceinline__ void cp16(void* smem_dst, const void* gmem_src) {
    uint32_t s = (uint32_t)__cvta_generic_to_shared(smem_dst);
    asm volatile("cp.async.cg.shared.global [%0], [%1], 16;" :: "r"(s), "l"(gmem_src));
}
__device__ __forceinline__ void cp_commit() {
    asm volatile("cp.async.commit_group;" ::: "memory");
}
template<int N>
__device__ __forceinline__ void cp_wait() {
    asm volatile("cp.async.wait_group %0;" :: "n"(N) : "memory");
}

__device__ __forceinline__ float block_sum(float v, float* red) {
    int tid = threadIdx.x, lane = tid & 31, warp = tid >> 5;
    int nw = blockDim.x >> 5;
    #pragma unroll
    for (int o = 16; o; o >>= 1) v += __shfl_xor_sync(0xffffffffu, v, o);
    if (lane == 0) red[warp] = v;
    __syncthreads();
    float r = (tid < nw) ? red[tid] : 0.0f;
    if (warp == 0) {
        #pragma unroll
        for (int o = 16; o; o >>= 1) r += __shfl_xor_sync(0xffffffffu, r, o);
        if (tid == 0) red[0] = r;
    }
    __syncthreads();
    float out = red[0];
    __syncthreads();
    return out;
}

__device__ __forceinline__ float block_max(float v, float* red) {
    int tid = threadIdx.x, lane = tid & 31, warp = tid >> 5;
    int nw = blockDim.x >> 5;
    #pragma unroll
    for (int o = 16; o; o >>= 1) v = fmaxf(v, __shfl_xor_sync(0xffffffffu, v, o));
    if (lane == 0) red[warp] = v;
    __syncthreads();
    float r = (tid < nw) ? red[tid] : -INFINITY;
    if (warp == 0) {
        #pragma unroll
        for (int o = 16; o; o >>= 1) r = fmaxf(r, __shfl_xor_sync(0xffffffffu, r, o));
        if (tid == 0) red[0] = r;
    }
    __syncthreads();
    float out = red[0];
    __syncthreads();
    return out;
}

// ---------------- embed + positional encoding -------------------------------
__global__ void embed_pe_kernel(const int* __restrict__ tokens,
                                const float* __restrict__ embed,
                                float* __restrict__ x) {
    const int row = blockIdx.x;
    const int t = row % T;
    const int tok = tokens[row];
    const float* erow = embed + (size_t)tok * D;
    float* xrow = x + (size_t)row * D;
    for (int i = threadIdx.x; i < D; i += blockDim.x) {
        int ip = i & ~1;
        double freq = exp(((double)ip / (double)D) * log(10000.0));
        double angle = (double)t / freq;
        float pe = (i & 1) ? (float)cos(angle) : (float)sin(angle);
        xrow[i] = erow[i] + pe;
    }
}

// ---------------- TF32 tensor-core GEMM, cp.async 4-stage pipeline ----------
// C = A @ B (+bias)(+relu). A:[M,K] row-major. B:[K,N] (NN) or [N,K] (TT).
// 128x128 block tile, BK=16, 8 warps, warp tile 32x64 (2x8 m16n8k8).
// CAUSAL: 0 none, 1 skip tiles above diagonal, 2 K-loop truncated at bm+128.
template<bool TRANSB, bool RELU, bool BIAS, int CAUSAL>
__global__ __launch_bounds__(256, 2) void gemm_tc(
    const float* __restrict__ A, const float* __restrict__ Bm,
    const float* __restrict__ bias, float* __restrict__ C,
    int M, int N, int K, long sA, long sB, long sC)
{
    constexpr int BM = 128, BN = 128, BK = 16;
    constexpr int NSTAGE = 4;
    constexpr int AST = 20;                   // As row stride (floats)
    constexpr int BST = TRANSB ? 20 : 136;    // Bs stride
    constexpr int ASZ = BM * AST;             // floats per A stage
    constexpr int BSZ = TRANSB ? BM * 20 : BK * 136;

    extern __shared__ float smem[];
    float* Asm = smem;                        // NSTAGE * ASZ
    float* Bsm = smem + NSTAGE * ASZ;         // NSTAGE * BSZ

    const int bm = blockIdx.y * BM;
    const int bn = blockIdx.x * BN;
    if (CAUSAL == 1 && bn > bm + BM - 1) return;

    const long bz = blockIdx.z;
    A  += bz * sA;
    Bm += bz * sB;
    C  += bz * sC;

    const int tid  = threadIdx.x;
    const int warp = tid >> 5, lane = tid & 31;
    const int g = lane >> 2, cg = lane & 3;
    const int wm = (warp >> 1) * 32, wn = (warp & 1) * 64;

    const int Kend = (CAUSAL == 2) ? min(K, bm + BM) : K;
    const int ktiles = Kend / BK;

    // per-thread load coordinates (2 float4 each for A and B)
    const int ar0 = tid >> 2, ac0 = (tid & 3) * 4;          // A row/col4, +64 rows for i=1
    const int br0 = tid >> 5, bc0 = (tid & 31) * 4;         // NN B row/col4, +8 rows for i=1

    auto issue = [&](int s) {
        if (s >= ktiles) { cp_commit(); return; }
        const int k0 = s * BK;
        const int slot = s & (NSTAGE - 1);
        float* As = Asm + slot * ASZ;
        float* Bs = Bsm + slot * BSZ;
        #pragma unroll
        for (int i = 0; i < 2; i++) {
            int r = ar0 + i * 64;
            cp16(&As[r * AST + ac0], A + (long)(bm + r) * K + k0 + ac0);
        }
        if (TRANSB) {
            #pragma unroll
            for (int i = 0; i < 2; i++) {
                int r = ar0 + i * 64;
                cp16(&Bs[r * BST + ac0], Bm + (long)(bn + r) * K + k0 + ac0);
            }
        } else {
            #pragma unroll
            for (int i = 0; i < 2; i++) {
                int r = br0 + i * 8;
                cp16(&Bs[r * BST + bc0], Bm + (long)(k0 + r) * N + bn + bc0);
            }
        }
        cp_commit();
    };

    float acc[2][8][4];
    #pragma unroll
    for (int mi = 0; mi < 2; mi++)
        #pragma unroll
        for (int ni = 0; ni < 8; ni++)
            #pragma unroll
            for (int j = 0; j < 4; j++) acc[mi][ni][j] = 0.0f;

    auto comp = [&](int slot) {
        const float* As = Asm + slot * ASZ;
        const float* Bs = Bsm + slot * BSZ;
        #pragma unroll
        for (int ks = 0; ks < 2; ks++) {
            const int kk = ks * 8 + cg;
            uint32_t af[2][4];
            #pragma unroll
            for (int mi = 0; mi < 2; mi++) {
                int r = wm + mi * 16 + g;
                af[mi][0] = __float_as_uint(As[r * AST + kk]);
                af[mi][1] = __float_as_uint(As[(r + 8) * AST + kk]);
                af[mi][2] = __float_as_uint(As[r * AST + kk + 4]);
                af[mi][3] = __float_as_uint(As[(r + 8) * AST + kk + 4]);
            }
            uint32_t bf[8][2];
            #pragma unroll
            for (int ni = 0; ni < 8; ni++) {
                int col = wn + ni * 8 + g;
                if (TRANSB) {
                    bf[ni][0] = __float_as_uint(Bs[col * BST + kk]);
                    bf[ni][1] = __float_as_uint(Bs[col * BST + kk + 4]);
                } else {
                    bf[ni][0] = __float_as_uint(Bs[kk * BST + col]);
                    bf[ni][1] = __float_as_uint(Bs[(kk + 4) * BST + col]);
                }
            }
            #pragma unroll
            for (int mi = 0; mi < 2; mi++)
                #pragma unroll
                for (int ni = 0; ni < 8; ni++)
                    asm volatile(
                        "mma.sync.aligned.m16n8k8.row.col.f32.tf32.tf32.f32 "
                        "{%0,%1,%2,%3}, {%4,%5,%6,%7}, {%8,%9}, {%0,%1,%2,%3};"
                        : "+f"(acc[mi][ni][0]), "+f"(acc[mi][ni][1]),
                          "+f"(acc[mi][ni][2]), "+f"(acc[mi][ni][3])
                        : "r"(af[mi][0]), "r"(af[mi][1]), "r"(af[mi][2]), "r"(af[mi][3]),
                          "r"(bf[ni][0]), "r"(bf[ni][1]));
        }
    };

    // prologue: fill NSTAGE-1 stages
    #pragma unroll
    for (int s = 0; s < NSTAGE - 1; s++) issue(s);

    for (int i = 0; i < ktiles; i++) {
        cp_wait<NSTAGE - 2>();
        __syncthreads();
        issue(i + NSTAGE - 1);       // writes slot (i-1)%NSTAGE, freed by the barrier
        comp(i & (NSTAGE - 1));
    }

    // epilogue
    #pragma unroll
    for (int mi = 0; mi < 2; mi++) {
        const long r0 = bm + wm + mi * 16 + g;
        #pragma unroll
        for (int ni = 0; ni < 8; ni++) {
            const int col = bn + wn + ni * 8 + cg * 2;
            float b0 = 0.0f, b1 = 0.0f;
            if (BIAS) { b0 = bias[col]; b1 = bias[col + 1]; }
            float2 v0 = make_float2(acc[mi][ni][0] + b0, acc[mi][ni][1] + b1);
            float2 v1 = make_float2(acc[mi][ni][2] + b0, acc[mi][ni][3] + b1);
            if (RELU) {
                v0.x = fmaxf(v0.x, 0.0f); v0.y = fmaxf(v0.y, 0.0f);
                v1.x = fmaxf(v1.x, 0.0f); v1.y = fmaxf(v1.y, 0.0f);
            }
            *(float2*)(C + r0 * N + col) = v0;
            *(float2*)(C + (r0 + 8) * N + col) = v1;
        }
    }
}

// ---------------- causal softmax over scores (in place) --------------------
__global__ void softmax_causal_kernel(float* __restrict__ scores) {
    const int t = blockIdx.x;
    const int b = blockIdx.y;
    float* row = scores + ((size_t)b * T + t) * T;
    const int n = t + 1;
    const float inv_scale = 0.03125f;
    __shared__ float red[32];
    const int tid = threadIdx.x;

    float m = -INFINITY;
    for (int s = tid; s < n; s += blockDim.x) m = fmaxf(m, row[s] * inv_scale);
    m = block_max(m, red);

    float sum = 0.0f;
    for (int s = tid; s < n; s += blockDim.x) {
        float e = expf(row[s] * inv_scale - m);
        row[s] = e;
        sum += e;
    }
    sum = block_sum(sum, red);
    const float inv = 1.0f / sum;

    for (int s = tid; s < n; s += blockDim.x) row[s] *= inv;
    for (int s = n + tid; s < T; s += blockDim.x) row[s] = 0.0f;
}

// ---------------- x = LayerNorm(x + y) * g + beta ---------------------------
__global__ void add_ln_kernel(float* __restrict__ x, const float* __restrict__ y,
                              const float* __restrict__ g, const float* __restrict__ beta) {
    const int row = blockIdx.x;
    __shared__ float buf[D];
    __shared__ float red[32];
    float* xr = x + (size_t)row * D;
    const float* yr = y + (size_t)row * D;
    const int tid = threadIdx.x;

    float sum = 0.0f;
    for (int i = tid; i < D; i += blockDim.x) {
        float v = xr[i] + yr[i];
        buf[i] = v;
        sum += v;
    }
    __syncthreads();
    sum = block_sum(sum, red);
    const float mu = sum * (1.0f / D);

    float vs = 0.0f;
    for (int i = tid; i < D; i += blockDim.x) {
        float d = buf[i] - mu;
        vs += d * d;
    }
    vs = block_sum(vs, red);
    const float rstd = rsqrtf(vs * (1.0f / D) + 1e-5f);

    for (int i = tid; i < D; i += blockDim.x)
        xr[i] = (buf[i] - mu) * rstd * g[i] + beta[i];
}

// ---------------- in-place log_softmax over vocab ---------------------------
__global__ void log_softmax_kernel(float* __restrict__ out) {
    float* row = out + (size_t)blockIdx.x * V;
    __shared__ float red[32];
    const int tid = threadIdx.x;

    float m = -INFINITY;
    for (int i = tid; i < V; i += blockDim.x) m = fmaxf(m, row[i]);
    m = block_max(m, red);

    float sum = 0.0f;
    for (int i = tid; i < V; i += blockDim.x) sum += expf(row[i] - m);
    sum = block_sum(sum, red);
    const float lse = m + logf(sum);

    for (int i = tid; i < V; i += blockDim.x) row[i] -= lse;
}

// ---------------- launch ----------------------------------------------------
#define SMEM_NN ((4 * (128 * 20) + 4 * (16 * 136)) * 4)   // 75776 B
#define SMEM_TT ((4 * (128 * 20) + 4 * (128 * 20)) * 4)   // 81920 B

extern "C" void kernel_launch(void* const* d_in, const int* in_sizes, int n_in,
                              void* d_out, int out_size) {
    const int*   tokens = (const int*)  d_in[0];
    const float* embed  = (const float*)d_in[1];
    const float* Wq     = (const float*)d_in[2];
    const float* bq     = (const float*)d_in[3];
    const float* Wk     = (const float*)d_in[4];
    const float* bk     = (const float*)d_in[5];
    const float* Wv     = (const float*)d_in[6];
    const float* bv     = (const float*)d_in[7];
    const float* g1     = (const float*)d_in[8];
    const float* beta1  = (const float*)d_in[9];
    const float* W1     = (const float*)d_in[10];
    const float* bf1    = (const float*)d_in[11];
    const float* W2     = (const float*)d_in[12];
    const float* bf2    = (const float*)d_in[13];
    const float* g2     = (const float*)d_in[14];
    const float* beta2  = (const float*)d_in[15];
    const float* Wout   = (const float*)d_in[16];
    const float* bout   = (const float*)d_in[17];
    float* out = (float*)d_out;

    float *x, *q, *k, *v, *attn, *scores, *h;
    cudaGetSymbolAddress((void**)&x,      g_x);
    cudaGetSymbolAddress((void**)&q,      g_q);
    cudaGetSymbolAddress((void**)&k,      g_k);
    cudaGetSymbolAddress((void**)&v,      g_v);
    cudaGetSymbolAddress((void**)&attn,   g_attn);
    cudaGetSymbolAddress((void**)&scores, g_scores);
    cudaGetSymbolAddress((void**)&h,      g_h);

    static bool attr_done = false;
    if (!attr_done) {
        cudaFuncSetAttribute(gemm_tc<false, false, true, 0>,
                             cudaFuncAttributeMaxDynamicSharedMemorySize, SMEM_NN);
        cudaFuncSetAttribute(gemm_tc<false, true, true, 0>,
                             cudaFuncAttributeMaxDynamicSharedMemorySize, SMEM_NN);
        cudaFuncSetAttribute(gemm_tc<false, false, false, 2>,
                             cudaFuncAttributeMaxDynamicSharedMemorySize, SMEM_NN);
        cudaFuncSetAttribute(gemm_tc<true, false, false, 1>,
                             cudaFuncAttributeMaxDynamicSharedMemorySize, SMEM_TT);
        attr_done = true;
    }

    embed_pe_kernel<<<BT, 256>>>(tokens, embed, x);

    for (int l = 0; l < L; ++l) {
        const float* wq = Wq + (size_t)l * D * D;
        const float* wk = Wk + (size_t)l * D * D;
        const float* wv = Wv + (size_t)l * D * D;

        gemm_tc<false, false, true, 0><<<dim3(D / 128, BT / 128, 1), 256, SMEM_NN>>>(
            x, wq, bq + (size_t)l * D, q, BT, D, D, 0, 0, 0);
        gemm_tc<false, false, true, 0><<<dim3(D / 128, BT / 128, 1), 256, SMEM_NN>>>(
            x, wk, bk + (size_t)l * D, k, BT, D, D, 0, 0, 0);
        gemm_tc<false, false, true, 0><<<dim3(D / 128, BT / 128, 1), 256, SMEM_NN>>>(
            x, wv, bv + (size_t)l * D, v, BT, D, D, 0, 0, 0);

        gemm_tc<true, false, false, 1><<<dim3(T / 128, T / 128, B), 256, SMEM_TT>>>(
            q, k, nullptr, scores, T, T, D,
            (long)T * D, (long)T * D, (long)T * T);

        softmax_causal_kernel<<<dim3(T, B, 1), 256>>>(scores);

        gemm_tc<false, false, false, 2><<<dim3(D / 128, T / 128, B), 256, SMEM_NN>>>(
            scores, v, nullptr, attn, T, D, T,
            (long)T * T, (long)T * D, (long)T * D);

        add_ln_kernel<<<BT, 256>>>(x, attn, g1 + (size_t)l * D, beta1 + (size_t)l * D);

        gemm_tc<false, true, true, 0><<<dim3(DF / 128, BT / 128, 1), 256, SMEM_NN>>>(
            x, W1 + (size_t)l * D * DF, bf1 + (size_t)l * DF, h, BT, DF, D, 0, 0, 0);
        gemm_tc<false, false, true, 0><<<dim3(D / 128, BT / 128, 1), 256, SMEM_NN>>>(
            h, W2 + (size_t)l * DF * D, bf2 + (size_t)l * D, attn, BT, D, DF, 0, 0, 0);

        add_ln_kernel<<<BT, 256>>>(x, attn, g2 + (size_t)l * D, beta2 + (size_t)l * D);
    }

    gemm_tc<false, false, true, 0><<<dim3(V / 128, BT / 128, 1), 256, SMEM_NN>>>(
        x, Wout, bout, out, BT, V, D, 0, 0, 0);
    log_softmax_kernel<<<BT, 256>>>(out);
}

// round 4
// speedup vs baseline: 3.3390x; 1.0016x over previous
#include <cuda_runtime.h>
#include <math.h>
#include <stdint.h>

#define B 2
#define T 2048
#define V 32000
#define D 1024
#define DF 4096
#define L 6
#define BT (B*T)

// ---------------- scratch (device globals; no allocation allowed) ----------
__device__ float g_x[BT * D];
__device__ float g_q[BT * D];
__device__ float g_k[BT * D];
__device__ float g_v[BT * D];
__device__ float g_attn[BT * D];
__device__ float g_scores[(size_t)B * T * T];
__device__ float g_h[BT * DF];

// ---------------- helpers ---------------------------------------------------
__device__ __forceinline__ void cp16(void* smem_dst, const void* gmem_src) {
    uint32_t s = (uint32_t)__cvta_generic_to_shared(smem_dst);
    asm volatile("cp.async.cg.shared.global [%0], [%1], 16;" :: "r"(s), "l"(gmem_src));
}
__device__ __forceinline__ void cp_commit() {
    asm volatile("cp.async.commit_group;" ::: "memory");
}
template<int N>
__device__ __forceinline__ void cp_wait() {
    asm volatile("cp.async.wait_group %0;" :: "n"(N) : "memory");
}

__device__ __forceinline__ float block_sum(float v, float* red) {
    int tid = threadIdx.x, lane = tid & 31, warp = tid >> 5;
    int nw = blockDim.x >> 5;
    #pragma unroll
    for (int o = 16; o; o >>= 1) v += __shfl_xor_sync(0xffffffffu, v, o);
    if (lane == 0) red[warp] = v;
    __syncthreads();
    float r = (tid < nw) ? red[tid] : 0.0f;
    if (warp == 0) {
        #pragma unroll
        for (int o = 16; o; o >>= 1) r += __shfl_xor_sync(0xffffffffu, r, o);
        if (tid == 0) red[0] = r;
    }
    __syncthreads();
    float out = red[0];
    __syncthreads();
    return out;
}

__device__ __forceinline__ float block_max(float v, float* red) {
    int tid = threadIdx.x, lane = tid & 31, warp = tid >> 5;
    int nw = blockDim.x >> 5;
    #pragma unroll
    for (int o = 16; o; o >>= 1) v = fmaxf(v, __shfl_xor_sync(0xffffffffu, v, o));
    if (lane == 0) red[warp] = v;
    __syncthreads();
    float r = (tid < nw) ? red[tid] : -INFINITY;
    if (warp == 0) {
        #pragma unroll
        for (int o = 16; o; o >>= 1) r = fmaxf(r, __shfl_xor_sync(0xffffffffu, r, o));
        if (tid == 0) red[0] = r;
    }
    __syncthreads();
    float out = red[0];
    __syncthreads();
    return out;
}

// ---------------- embed + positional encoding -------------------------------
__global__ void embed_pe_kernel(const int* __restrict__ tokens,
                                const float* __restrict__ embed,
                                float* __restrict__ x) {
    const int row = blockIdx.x;
    const int t = row % T;
    const int tok = tokens[row];
    const float* erow = embed + (size_t)tok * D;
    float* xrow = x + (size_t)row * D;
    for (int i = threadIdx.x; i < D; i += blockDim.x) {
        int ip = i & ~1;
        double freq = exp(((double)ip / (double)D) * log(10000.0));
        double angle = (double)t / freq;
        float pe = (i & 1) ? (float)cos(angle) : (float)sin(angle);
        xrow[i] = erow[i] + pe;
    }
}

// ---------------- TF32 tensor-core GEMM, cp.async 4-stage pipeline ----------
// C = A @ B (+bias)(+relu). A:[M,K] row-major. B:[K,N] (NN) or [N,K] (TT).
// 128x128 block tile, BK=16, 8 warps, warp tile 32x64 (2x8 m16n8k8).
// CAUSAL: 0 none, 1 skip tiles above diagonal, 2 K-loop truncated at bm+128.
template<bool TRANSB, bool RELU, bool BIAS, int CAUSAL>
__global__ __launch_bounds__(256, 2) void gemm_tc(
    const float* __restrict__ A, const float* __restrict__ Bm,
    const float* __restrict__ bias, float* __restrict__ C,
    int M, int N, int K, long sA, long sB, long sC)
{
    constexpr int BM = 128, BN = 128, BK = 16;
    constexpr int NSTAGE = 4;
    constexpr int AST = 20;                   // As row stride (floats)
    constexpr int BST = TRANSB ? 20 : 136;    // Bs stride
    constexpr int ASZ = BM * AST;             // floats per A stage
    constexpr int BSZ = TRANSB ? BM * 20 : BK * 136;

    extern __shared__ float smem[];
    float* Asm = smem;                        // NSTAGE * ASZ
    float* Bsm = smem + NSTAGE * ASZ;         // NSTAGE * BSZ

    const int bm = blockIdx.y * BM;
    const int bn = blockIdx.x * BN;
    if (CAUSAL == 1 && bn > bm + BM - 1) return;

    const long bz = blockIdx.z;
    A  += bz * sA;
    Bm += bz * sB;
    C  += bz * sC;

    const int tid  = threadIdx.x;
    const int warp = tid >> 5, lane = tid & 31;
    const int g = lane >> 2, cg = lane & 3;
    const int wm = (warp >> 1) * 32, wn = (warp & 1) * 64;

    const int Kend = (CAUSAL == 2) ? min(K, bm + BM) : K;
    const int ktiles = Kend / BK;

    // per-thread load coordinates (2 float4 each for A and B)
    const int ar0 = tid >> 2, ac0 = (tid & 3) * 4;          // A row/col4, +64 rows for i=1
    const int br0 = tid >> 5, bc0 = (tid & 31) * 4;         // NN B row/col4, +8 rows for i=1

    auto issue = [&](int s) {
        if (s >= ktiles) { cp_commit(); return; }
        const int k0 = s * BK;
        const int slot = s & (NSTAGE - 1);
        float* As = Asm + slot * ASZ;
        float* Bs = Bsm + slot * BSZ;
        #pragma unroll
        for (int i = 0; i < 2; i++) {
            int r = ar0 + i * 64;
            cp16(&As[r * AST + ac0], A + (long)(bm + r) * K + k0 + ac0);
        }
        if (TRANSB) {
            #pragma unroll
            for (int i = 0; i < 2; i++) {
                int r = ar0 + i * 64;
                cp16(&Bs[r * BST + ac0], Bm + (long)(bn + r) * K + k0 + ac0);
            }
        } else {
            #pragma unroll
            for (int i = 0; i < 2; i++) {
                int r = br0 + i * 8;
                cp16(&Bs[r * BST + bc0], Bm + (long)(k0 + r) * N + bn + bc0);
            }
        }
        cp_commit();
    };

    float acc[2][8][4];
    #pragma unroll
    for (int mi = 0; mi < 2; mi++)
        #pragma unroll
        for (int ni = 0; ni < 8; ni++)
            #pragma unroll
            for (int j = 0; j < 4; j++) acc[mi][ni][j] = 0.0f;

    auto comp = [&](int slot) {
        const float* As = Asm + slot * ASZ;
        const float* Bs = Bsm + slot * BSZ;
        #pragma unroll
        for (int ks = 0; ks < 2; ks++) {
            const int kk = ks * 8 + cg;
            uint32_t af[2][4];
            #pragma unroll
            for (int mi = 0; mi < 2; mi++) {
                int r = wm + mi * 16 + g;
                af[mi][0] = __float_as_uint(As[r * AST + kk]);
                af[mi][1] = __float_as_uint(As[(r + 8) * AST + kk]);
                af[mi][2] = __float_as_uint(As[r * AST + kk + 4]);
                af[mi][3] = __float_as_uint(As[(r + 8) * AST + kk + 4]);
            }
            uint32_t bf[8][2];
            #pragma unroll
            for (int ni = 0; ni < 8; ni++) {
                int col = wn + ni * 8 + g;
                if (TRANSB) {
                    bf[ni][0] = __float_as_uint(Bs[col * BST + kk]);
                    bf[ni][1] = __float_as_uint(Bs[col * BST + kk + 4]);
                } else {
                    bf[ni][0] = __float_as_uint(Bs[kk * BST + col]);
                    bf[ni][1] = __float_as_uint(Bs[(kk + 4) * BST + col]);
                }
            }
            #pragma unroll
            for (int mi = 0; mi < 2; mi++)
                #pragma unroll
                for (int ni = 0; ni < 8; ni++)
                    asm volatile(
                        "mma.sync.aligned.m16n8k8.row.col.f32.tf32.tf32.f32 "
                        "{%0,%1,%2,%3}, {%4,%5,%6,%7}, {%8,%9}, {%0,%1,%2,%3};"
                        : "+f"(acc[mi][ni][0]), "+f"(acc[mi][ni][1]),
                          "+f"(acc[mi][ni][2]), "+f"(acc[mi][ni][3])
                        : "r"(af[mi][0]), "r"(af[mi][1]), "r"(af[mi][2]), "r"(af[mi][3]),
                          "r"(bf[ni][0]), "r"(bf[ni][1]));
        }
    };

    // prologue: fill NSTAGE-1 stages
    #pragma unroll
    for (int s = 0; s < NSTAGE - 1; s++) issue(s);

    for (int i = 0; i < ktiles; i++) {
        cp_wait<NSTAGE - 2>();
        __syncthreads();
        issue(i + NSTAGE - 1);       // writes slot (i-1)%NSTAGE, freed by the barrier
        comp(i & (NSTAGE - 1));
    }

    // epilogue
    #pragma unroll
    for (int mi = 0; mi < 2; mi++) {
        const long r0 = bm + wm + mi * 16 + g;
        #pragma unroll
        for (int ni = 0; ni < 8; ni++) {
            const int col = bn + wn + ni * 8 + cg * 2;
            float b0 = 0.0f, b1 = 0.0f;
            if (BIAS) { b0 = bias[col]; b1 = bias[col + 1]; }
            float2 v0 = make_float2(acc[mi][ni][0] + b0, acc[mi][ni][1] + b1);
            float2 v1 = make_float2(acc[mi][ni][2] + b0, acc[mi][ni][3] + b1);
            if (RELU) {
                v0.x = fmaxf(v0.x, 0.0f); v0.y = fmaxf(v0.y, 0.0f);
                v1.x = fmaxf(v1.x, 0.0f); v1.y = fmaxf(v1.y, 0.0f);
            }
            *(float2*)(C + r0 * N + col) = v0;
            *(float2*)(C + (r0 + 8) * N + col) = v1;
        }
    }
}

// ---------------- causal softmax over scores (in place) --------------------
__global__ void softmax_causal_kernel(float* __restrict__ scores) {
    const int t = blockIdx.x;
    const int b = blockIdx.y;
    float* row = scores + ((size_t)b * T + t) * T;
    const int n = t + 1;
    const float inv_scale = 0.03125f;
    __shared__ float red[32];
    const int tid = threadIdx.x;

    float m = -INFINITY;
    for (int s = tid; s < n; s += blockDim.x) m = fmaxf(m, row[s] * inv_scale);
    m = block_max(m, red);

    float sum = 0.0f;
    for (int s = tid; s < n; s += blockDim.x) {
        float e = expf(row[s] * inv_scale - m);
        row[s] = e;
        sum += e;
    }
    sum = block_sum(sum, red);
    const float inv = 1.0f / sum;

    for (int s = tid; s < n; s += blockDim.x) row[s] *= inv;
    for (int s = n + tid; s < T; s += blockDim.x) row[s] = 0.0f;
}

// ---------------- x = LayerNorm(x + y) * g + beta ---------------------------
__global__ void add_ln_kernel(float* __restrict__ x, const float* __restrict__ y,
                              const float* __restrict__ g, const float* __restrict__ beta) {
    const int row = blockIdx.x;
    __shared__ float buf[D];
    __shared__ float red[32];
    float* xr = x + (size_t)row * D;
    const float* yr = y + (size_t)row * D;
    const int tid = threadIdx.x;

    float sum = 0.0f;
    for (int i = tid; i < D; i += blockDim.x) {
        float v = xr[i] + yr[i];
        buf[i] = v;
        sum += v;
    }
    __syncthreads();
    sum = block_sum(sum, red);
    const float mu = sum * (1.0f / D);

    float vs = 0.0f;
    for (int i = tid; i < D; i += blockDim.x) {
        float d = buf[i] - mu;
        vs += d * d;
    }
    vs = block_sum(vs, red);
    const float rstd = rsqrtf(vs * (1.0f / D) + 1e-5f);

    for (int i = tid; i < D; i += blockDim.x)
        xr[i] = (buf[i] - mu) * rstd * g[i] + beta[i];
}

// ---------------- in-place log_softmax over vocab ---------------------------
__global__ void log_softmax_kernel(float* __restrict__ out) {
    float* row = out + (size_t)blockIdx.x * V;
    __shared__ float red[32];
    const int tid = threadIdx.x;

    float m = -INFINITY;
    for (int i = tid; i < V; i += blockDim.x) m = fmaxf(m, row[i]);
    m = block_max(m, red);

    float sum = 0.0f;
    for (int i = tid; i < V; i += blockDim.x) sum += expf(row[i] - m);
    sum = block_sum(sum, red);
    const float lse = m + logf(sum);

    for (int i = tid; i < V; i += blockDim.x) row[i] -= lse;
}

// ---------------- launch ----------------------------------------------------
#define SMEM_NN ((4 * (128 * 20) + 4 * (16 * 136)) * 4)   // 75776 B
#define SMEM_TT ((4 * (128 * 20) + 4 * (128 * 20)) * 4)   // 81920 B

extern "C" void kernel_launch(void* const* d_in, const int* in_sizes, int n_in,
                              void* d_out, int out_size) {
    const int*   tokens = (const int*)  d_in[0];
    const float* embed  = (const float*)d_in[1];
    const float* Wq     = (const float*)d_in[2];
    const float* bq     = (const float*)d_in[3];
    const float* Wk     = (const float*)d_in[4];
    const float* bk     = (const float*)d_in[5];
    const float* Wv     = (const float*)d_in[6];
    const float* bv     = (const float*)d_in[7];
    const float* g1     = (const float*)d_in[8];
    const float* beta1  = (const float*)d_in[9];
    const float* W1     = (const float*)d_in[10];
    const float* bf1    = (const float*)d_in[11];
    const float* W2     = (const float*)d_in[12];
    const float* bf2    = (const float*)d_in[13];
    const float* g2     = (const float*)d_in[14];
    const float* beta2  = (const float*)d_in[15];
    const float* Wout   = (const float*)d_in[16];
    const float* bout   = (const float*)d_in[17];
    float* out = (float*)d_out;

    float *x, *q, *k, *v, *attn, *scores, *h;
    cudaGetSymbolAddress((void**)&x,      g_x);
    cudaGetSymbolAddress((void**)&q,      g_q);
    cudaGetSymbolAddress((void**)&k,      g_k);
    cudaGetSymbolAddress((void**)&v,      g_v);
    cudaGetSymbolAddress((void**)&attn,   g_attn);
    cudaGetSymbolAddress((void**)&scores, g_scores);
    cudaGetSymbolAddress((void**)&h,      g_h);

    static bool attr_done = false;
    if (!attr_done) {
        cudaFuncSetAttribute(gemm_tc<false, false, true, 0>,
                             cudaFuncAttributeMaxDynamicSharedMemorySize, SMEM_NN);
        cudaFuncSetAttribute(gemm_tc<false, true, true, 0>,
                             cudaFuncAttributeMaxDynamicSharedMemorySize, SMEM_NN);
        cudaFuncSetAttribute(gemm_tc<false, false, false, 2>,
                             cudaFuncAttributeMaxDynamicSharedMemorySize, SMEM_NN);
        cudaFuncSetAttribute(gemm_tc<true, false, false, 1>,
                             cudaFuncAttributeMaxDynamicSharedMemorySize, SMEM_TT);
        attr_done = true;
    }

    embed_pe_kernel<<<BT, 256>>>(tokens, embed, x);

    for (int l = 0; l < L; ++l) {
        const float* wq = Wq + (size_t)l * D * D;
        const float* wk = Wk + (size_t)l * D * D;
        const float* wv = Wv + (size_t)l * D * D;

        gemm_tc<false, false, true, 0><<<dim3(D / 128, BT / 128, 1), 256, SMEM_NN>>>(
            x, wq, bq + (size_t)l * D, q, BT, D, D, 0, 0, 0);
        gemm_tc<false, false, true, 0><<<dim3(D / 128, BT / 128, 1), 256, SMEM_NN>>>(
            x, wk, bk + (size_t)l * D, k, BT, D, D, 0, 0, 0);
        gemm_tc<false, false, true, 0><<<dim3(D / 128, BT / 128, 1), 256, SMEM_NN>>>(
            x, wv, bv + (size_t)l * D, v, BT, D, D, 0, 0, 0);

        gemm_tc<true, false, false, 1><<<dim3(T / 128, T / 128, B), 256, SMEM_TT>>>(
            q, k, nullptr, scores, T, T, D,
            (long)T * D, (long)T * D, (long)T * T);

        softmax_causal_kernel<<<dim3(T, B, 1), 256>>>(scores);

        gemm_tc<false, false, false, 2><<<dim3(D / 128, T / 128, B), 256, SMEM_NN>>>(
            scores, v, nullptr, attn, T, D, T,
            (long)T * T, (long)T * D, (long)T * D);

        add_ln_kernel<<<BT, 256>>>(x, attn, g1 + (size_t)l * D, beta1 + (size_t)l * D);

        gemm_tc<false, true, true, 0><<<dim3(DF / 128, BT / 128, 1), 256, SMEM_NN>>>(
            x, W1 + (size_t)l * D * DF, bf1 + (size_t)l * DF, h, BT, DF, D, 0, 0, 0);
        gemm_tc<false, false, true, 0><<<dim3(D / 128, BT / 128, 1), 256, SMEM_NN>>>(
            h, W2 + (size_t)l * DF * D, bf2 + (size_t)l * D, attn, BT, D, DF, 0, 0, 0);

        add_ln_kernel<<<BT, 256>>>(x, attn, g2 + (size_t)l * D, beta2 + (size_t)l * D);
    }

    gemm_tc<false, false, true, 0><<<dim3(V / 128, BT / 128, 1), 256, SMEM_NN>>>(
        x, Wout, bout, out, BT, V, D, 0, 0, 0);
    log_softmax_kernel<<<BT, 256>>>(out);
}

// round 6
// speedup vs baseline: 3.8091x; 1.1408x over previous
#include <cuda_runtime.h>
#include <math.h>
#include <stdint.h>

#define B 2
#define T 2048
#define V 32000
#define D 1024
#define DF 4096
#define L 6
#define BT (B*T)

// ---------------- scratch (device globals; no allocation allowed) ----------
__device__ __align__(1024) float g_x[(size_t)BT * D];
__device__ __align__(1024) float g_qkv[(size_t)3 * BT * D];
__device__ __align__(1024) float g_vT[(size_t)BT * D];
__device__ __align__(1024) float g_attn[(size_t)BT * D];
__device__ __align__(1024) float g_scores[(size_t)B * T * T];
__device__ __align__(1024) float g_h[(size_t)BT * DF];
__device__ __align__(1024) float g_wqkvT[(size_t)L * 3 * D * D];
__device__ __align__(1024) float g_w1T[(size_t)L * DF * D];
__device__ __align__(1024) float g_w2T[(size_t)L * D * DF];
__device__ __align__(1024) float g_woutT[(size_t)V * D];

// ---------------- low-level helpers -----------------------------------------
__device__ __forceinline__ uint32_t smem_u32(const void* p) {
    uint32_t a;
    asm("{ .reg .u64 t; cvta.to.shared.u64 t, %1; cvt.u32.u64 %0, t; }" : "=r"(a) : "l"(p));
    return a;
}
__device__ __forceinline__ void cp16(void* smem_dst, const void* gmem_src) {
    uint32_t s = (uint32_t)__cvta_generic_to_shared(smem_dst);
    asm volatile("cp.async.cg.shared.global [%0], [%1], 16;" :: "r"(s), "l"(gmem_src));
}
__device__ __forceinline__ void cp_commit() {
    asm volatile("cp.async.commit_group;" ::: "memory");
}
template<int N>
__device__ __forceinline__ void cp_wait() {
    asm volatile("cp.async.wait_group %0;" :: "n"(N) : "memory");
}
__device__ __forceinline__ void ldsm4(uint32_t addr, uint32_t& r0, uint32_t& r1,
                                      uint32_t& r2, uint32_t& r3) {
    asm volatile("ldmatrix.sync.aligned.m8n8.x4.shared.b16 {%0,%1,%2,%3}, [%4];"
                 : "=r"(r0), "=r"(r1), "=r"(r2), "=r"(r3) : "r"(addr));
}

__device__ __forceinline__ float block_sum(float v, float* red) {
    int tid = threadIdx.x, lane = tid & 31, warp = tid >> 5;
    int nw = blockDim.x >> 5;
    #pragma unroll
    for (int o = 16; o; o >>= 1) v += __shfl_xor_sync(0xffffffffu, v, o);
    if (lane == 0) red[warp] = v;
    __syncthreads();
    float r = (tid < nw) ? red[tid] : 0.0f;
    if (warp == 0) {
        #pragma unroll
        for (int o = 16; o; o >>= 1) r += __shfl_xor_sync(0xffffffffu, r, o);
        if (tid == 0) red[0] = r;
    }
    __syncthreads();
    float out = red[0];
    __syncthreads();
    return out;
}
__device__ __forceinline__ float block_max(float v, float* red) {
    int tid = threadIdx.x, lane = tid & 31, warp = tid >> 5;
    int nw = blockDim.x >> 5;
    #pragma unroll
    for (int o = 16; o; o >>= 1) v = fmaxf(v, __shfl_xor_sync(0xffffffffu, v, o));
    if (lane == 0) red[warp] = v;
    __syncthreads();
    float r = (tid < nw) ? red[tid] : -INFINITY;
    if (warp == 0) {
        #pragma unroll
        for (int o = 16; o; o >>= 1) r = fmaxf(r, __shfl_xor_sync(0xffffffffu, r, o));
        if (tid == 0) red[0] = r;
    }
    __syncthreads();
    float out = red[0];
    __syncthreads();
    return out;
}

// ---------------- embed + positional encoding -------------------------------
__global__ void embed_pe_kernel(const int* __restrict__ tokens,
                                const float* __restrict__ embed,
                                float* __restrict__ x) {
    const int row = blockIdx.x;
    const int t = row % T;
    const int tok = tokens[row];
    const float* erow = embed + (size_t)tok * D;
    float* xrow = x + (size_t)row * D;
    for (int i = threadIdx.x; i < D; i += blockDim.x) {
        int ip = i & ~1;
        double freq = exp(((double)ip / (double)D) * log(10000.0));
        double angle = (double)t / freq;
        float pe = (i & 1) ? (float)cos(angle) : (float)sin(angle);
        xrow[i] = erow[i] + pe;
    }
}

// ---------------- transpose [R,C] -> [C,R], batched --------------------------
__global__ void transpose_kernel(const float* __restrict__ in, float* __restrict__ out,
                                 int R, int C, long inStride, long outStride) {
    __shared__ float tile[32][33];
    const long zi = blockIdx.z;
    in  += zi * inStride;
    out += zi * outStride;
    const int c0 = blockIdx.x * 32, r0 = blockIdx.y * 32;
    const int tx = threadIdx.x, ty = threadIdx.y;   // 32 x 8
    #pragma unroll
    for (int j = 0; j < 32; j += 8)
        tile[ty + j][tx] = in[(long)(r0 + ty + j) * C + c0 + tx];
    __syncthreads();
    #pragma unroll
    for (int j = 0; j < 32; j += 8)
        out[(long)(c0 + ty + j) * R + r0 + tx] = tile[tx][ty + j];
}

// ---------------- TF32 mma.sync TT GEMM, ldmatrix fragments ------------------
// C[M,N] = A[M,K] @ Bt[N,K]^T (+bias)(+relu). A,Bt row-major K-major.
// 128x128 CTA tile, BK=32, 3-stage cp.async, 8 warps (warp tile 32x64).
// CAUSAL: 0 none, 1 skip tiles above diagonal, 2 K truncated at bm+128.
#define AST 36
#define STAGEF (256 * AST)                 // A(128 rows) + B(128 rows)
#define GEMM_SMEM (3 * STAGEF * 4)         // 110592 B

template<int CAUSAL, bool RELU, bool BIAS>
__global__ __launch_bounds__(256, 2) void gemm_tt(
    const float* __restrict__ A, const float* __restrict__ Bt,
    const float* __restrict__ b0, const float* __restrict__ b1, const float* __restrict__ b2,
    float* __restrict__ C, int N, int K, long sA, long sB, long sC)
{
    extern __shared__ float sm[];

    const int bm = blockIdx.y * 128;
    const int bn = blockIdx.x * 128;
    if (CAUSAL == 1 && bn > bm + 127) return;
    const int z = blockIdx.z;
    A  += (long)z * sA;
    Bt += (long)z * sB;
    C  += (long)z * sC;

    const int tid = threadIdx.x, warp = tid >> 5, lane = tid & 31;
    const int g = lane >> 2, cg = lane & 3;
    const int wm = (warp >> 1) * 32, wn = (warp & 1) * 64;
    const int lr = lane & 7, qd = lane >> 3;

    const int Kend = (CAUSAL == 2) ? min(K, bm + 128) : K;
    const int KT = Kend >> 5;

    const uint32_t sbase = smem_u32(sm);

    // ldmatrix per-lane byte offsets within a stage
    uint32_t aoff[2], boff[4];
    #pragma unroll
    for (int mi = 0; mi < 2; mi++)
        aoff[mi] = (uint32_t)(((wm + mi * 16 + (qd & 1) * 8 + lr) * AST + (qd >> 1) * 4) * 4);
    #pragma unroll
    for (int nip = 0; nip < 4; nip++)
        boff[nip] = (uint32_t)(((128 + wn + nip * 16 + (qd >> 1) * 8 + lr) * AST + (qd & 1) * 4) * 4);

    auto issue = [&](int s) {
        if (s >= KT) { cp_commit(); return; }
        const int k0 = s << 5;
        float* As = sm + (s % 3) * STAGEF;
        float* Bs = As + 128 * AST;
        #pragma unroll
        for (int i = 0; i < 4; i++) {
            int idx = tid + i * 256;
            int r = idx >> 3, c = (idx & 7) << 2;
            cp16(&As[r * AST + c], A + (long)(bm + r) * K + k0 + c);
            cp16(&Bs[r * AST + c], Bt + (long)(bn + r) * K + k0 + c);
        }
        cp_commit();
    };

    float acc[2][8][4];
    #pragma unroll
    for (int mi = 0; mi < 2; mi++)
        #pragma unroll
        for (int ni = 0; ni < 8; ni++)
            #pragma unroll
            for (int j = 0; j < 4; j++) acc[mi][ni][j] = 0.0f;

    auto comp = [&](int slot) {
        const uint32_t st = sbase + (uint32_t)slot * (STAGEF * 4);
        #pragma unroll
        for (int ks = 0; ks < 4; ks++) {
            uint32_t af[2][4], bf[8][2];
            #pragma unroll
            for (int mi = 0; mi < 2; mi++)
                ldsm4(st + aoff[mi] + ks * 32, af[mi][0], af[mi][1], af[mi][2], af[mi][3]);
            #pragma unroll
            for (int nip = 0; nip < 4; nip++)
                ldsm4(st + boff[nip] + ks * 32,
                      bf[2 * nip][0], bf[2 * nip][1], bf[2 * nip + 1][0], bf[2 * nip + 1][1]);
            #pragma unroll
            for (int mi = 0; mi < 2; mi++)
                #pragma unroll
                for (int ni = 0; ni < 8; ni++)
                    asm volatile(
                        "mma.sync.aligned.m16n8k8.row.col.f32.tf32.tf32.f32 "
                        "{%0,%1,%2,%3}, {%4,%5,%6,%7}, {%8,%9}, {%0,%1,%2,%3};"
                        : "+f"(acc[mi][ni][0]), "+f"(acc[mi][ni][1]),
                          "+f"(acc[mi][ni][2]), "+f"(acc[mi][ni][3])
                        : "r"(af[mi][0]), "r"(af[mi][1]), "r"(af[mi][2]), "r"(af[mi][3]),
                          "r"(bf[ni][0]), "r"(bf[ni][1]));
        }
    };

    issue(0);
    issue(1);
    for (int i = 0; i < KT; i++) {
        cp_wait<1>();
        __syncthreads();
        issue(i + 2);
        comp(i % 3);
    }

    // epilogue
    const float* bias = BIAS ? (z == 0 ? b0 : (z == 1 ? b1 : b2)) : b0;
    #pragma unroll
    for (int mi = 0; mi < 2; mi++) {
        const long r0 = bm + wm + mi * 16 + g;
        #pragma unroll
        for (int ni = 0; ni < 8; ni++) {
            const int col = bn + wn + ni * 8 + cg * 2;
            float bb0 = 0.0f, bb1 = 0.0f;
            if (BIAS) { bb0 = bias[col]; bb1 = bias[col + 1]; }
            float2 v0 = make_float2(acc[mi][ni][0] + bb0, acc[mi][ni][1] + bb1);
            float2 v1 = make_float2(acc[mi][ni][2] + bb0, acc[mi][ni][3] + bb1);
            if (RELU) {
                v0.x = fmaxf(v0.x, 0.0f); v0.y = fmaxf(v0.y, 0.0f);
                v1.x = fmaxf(v1.x, 0.0f); v1.y = fmaxf(v1.y, 0.0f);
            }
            *(float2*)(C + r0 * N + col) = v0;
            *(float2*)(C + (r0 + 8) * N + col) = v1;
        }
    }
}

// ---------------- causal softmax over scores (in place) ----------------------
__global__ void softmax_causal_kernel(float* __restrict__ scores) {
    const int t = blockIdx.x;
    const int b = blockIdx.y;
    float* row = scores + ((size_t)b * T + t) * T;
    const int n = t + 1;
    const float inv_scale = 0.03125f;   // 1/sqrt(1024)
    __shared__ float red[32];
    const int tid = threadIdx.x;

    float m = -INFINITY;
    for (int s = tid; s < n; s += blockDim.x) m = fmaxf(m, row[s] * inv_scale);
    m = block_max(m, red);

    float sum = 0.0f;
    for (int s = tid; s < n; s += blockDim.x) {
        float e = expf(row[s] * inv_scale - m);
        row[s] = e;
        sum += e;
    }
    sum = block_sum(sum, red);
    const float inv = 1.0f / sum;

    for (int s = tid; s < n; s += blockDim.x) row[s] *= inv;
    for (int s = n + tid; s < T; s += blockDim.x) row[s] = 0.0f;
}

// ---------------- x = LayerNorm(x + y) * g + beta -----------------------------
__global__ void add_ln_kernel(float* __restrict__ x, const float* __restrict__ y,
                              const float* __restrict__ g, const float* __restrict__ beta) {
    const int row = blockIdx.x;
    __shared__ float buf[D];
    __shared__ float red[32];
    float* xr = x + (size_t)row * D;
    const float* yr = y + (size_t)row * D;
    const int tid = threadIdx.x;

    float sum = 0.0f;
    for (int i = tid; i < D; i += blockDim.x) {
        float v = xr[i] + yr[i];
        buf[i] = v;
        sum += v;
    }
    __syncthreads();
    sum = block_sum(sum, red);
    const float mu = sum * (1.0f / D);

    float vs = 0.0f;
    for (int i = tid; i < D; i += blockDim.x) {
        float d = buf[i] - mu;
        vs += d * d;
    }
    vs = block_sum(vs, red);
    const float rstd = rsqrtf(vs * (1.0f / D) + 1e-5f);

    for (int i = tid; i < D; i += blockDim.x)
        xr[i] = (buf[i] - mu) * rstd * g[i] + beta[i];
}

// ---------------- in-place log_softmax over vocab -----------------------------
__global__ void log_softmax_kernel(float* __restrict__ out) {
    float* row = out + (size_t)blockIdx.x * V;
    __shared__ float red[32];
    const int tid = threadIdx.x;

    float m = -INFINITY, s = 0.0f;
    for (int i = tid; i < V; i += blockDim.x) {
        float v = row[i];
        if (v > m) { s = s * expf(m - v) + 1.0f; m = v; }
        else s += expf(v - m);
    }
    float M = block_max(m, red);
    float sum = block_sum(s * expf(m - M), red);
    const float lse = M + logf(sum);

    for (int i = tid; i < V; i += blockDim.x) row[i] -= lse;
}

// ---------------- launch -------------------------------------------------------
extern "C" void kernel_launch(void* const* d_in, const int* in_sizes, int n_in,
                              void* d_out, int out_size) {
    const int*   tokens = (const int*)  d_in[0];
    const float* embed  = (const float*)d_in[1];
    const float* Wq     = (const float*)d_in[2];
    const float* bq     = (const float*)d_in[3];
    const float* Wk     = (const float*)d_in[4];
    const float* bk     = (const float*)d_in[5];
    const float* Wv     = (const float*)d_in[6];
    const float* bv     = (const float*)d_in[7];
    const float* g1     = (const float*)d_in[8];
    const float* beta1  = (const float*)d_in[9];
    const float* W1     = (const float*)d_in[10];
    const float* bf1    = (const float*)d_in[11];
    const float* W2     = (const float*)d_in[12];
    const float* bf2    = (const float*)d_in[13];
    const float* g2     = (const float*)d_in[14];
    const float* beta2  = (const float*)d_in[15];
    const float* Wout   = (const float*)d_in[16];
    const float* bout   = (const float*)d_in[17];
    float* out = (float*)d_out;

    float *x, *qkv, *vT, *attn, *scores, *h, *wqkvT, *w1T, *w2T, *woutT;
    cudaGetSymbolAddress((void**)&x,      g_x);
    cudaGetSymbolAddress((void**)&qkv,    g_qkv);
    cudaGetSymbolAddress((void**)&vT,     g_vT);
    cudaGetSymbolAddress((void**)&attn,   g_attn);
    cudaGetSymbolAddress((void**)&scores, g_scores);
    cudaGetSymbolAddress((void**)&h,      g_h);
    cudaGetSymbolAddress((void**)&wqkvT,  g_wqkvT);
    cudaGetSymbolAddress((void**)&w1T,    g_w1T);
    cudaGetSymbolAddress((void**)&w2T,    g_w2T);
    cudaGetSymbolAddress((void**)&woutT,  g_woutT);
    float* q = qkv;
    float* k = qkv + (size_t)BT * D;
    float* v = qkv + (size_t)2 * BT * D;

    cudaFuncSetAttribute(gemm_tt<0, false, true>,  cudaFuncAttributeMaxDynamicSharedMemorySize, GEMM_SMEM);
    cudaFuncSetAttribute(gemm_tt<0, true,  true>,  cudaFuncAttributeMaxDynamicSharedMemorySize, GEMM_SMEM);
    cudaFuncSetAttribute(gemm_tt<1, false, false>, cudaFuncAttributeMaxDynamicSharedMemorySize, GEMM_SMEM);
    cudaFuncSetAttribute(gemm_tt<2, false, false>, cudaFuncAttributeMaxDynamicSharedMemorySize, GEMM_SMEM);

    // ---- weight transposes to [N,K] K-major ----
    dim3 tb(32, 8);
    transpose_kernel<<<dim3(D / 32, D / 32, L), tb>>>(Wq, wqkvT + 0 * (size_t)D * D, D, D, (long)D * D, (long)3 * D * D);
    transpose_kernel<<<dim3(D / 32, D / 32, L), tb>>>(Wk, wqkvT + 1 * (size_t)D * D, D, D, (long)D * D, (long)3 * D * D);
    transpose_kernel<<<dim3(D / 32, D / 32, L), tb>>>(Wv, wqkvT + 2 * (size_t)D * D, D, D, (long)D * D, (long)3 * D * D);
    transpose_kernel<<<dim3(DF / 32, D / 32, L), tb>>>(W1, w1T, D, DF, (long)D * DF, (long)DF * D);
    transpose_kernel<<<dim3(D / 32, DF / 32, L), tb>>>(W2, w2T, DF, D, (long)DF * D, (long)D * DF);
    transpose_kernel<<<dim3(V / 32, D / 32, 1), tb>>>(Wout, woutT, D, V, 0, 0);

    embed_pe_kernel<<<BT, 256>>>(tokens, embed, x);

    for (int l = 0; l < L; ++l) {
        // fused QKV (z = 0,1,2 selects weight slice + bias + output slice)
        gemm_tt<0, false, true><<<dim3(D / 128, BT / 128, 3), 256, GEMM_SMEM>>>(
            x, wqkvT + (size_t)l * 3 * D * D,
            bq + (size_t)l * D, bk + (size_t)l * D, bv + (size_t)l * D,
            qkv, D, D, 0, (long)D * D, (long)BT * D);

        // scores = q @ k^T per batch (k is already [T,D] = [N,K])
        gemm_tt<1, false, false><<<dim3(T / 128, T / 128, B), 256, GEMM_SMEM>>>(
            q, k, nullptr, nullptr, nullptr,
            scores, T, D, (long)T * D, (long)T * D, (long)T * T);

        softmax_causal_kernel<<<dim3(T, B, 1), 256>>>(scores);

        // v^T per batch: [T,D] -> [D,T]
        transpose_kernel<<<dim3(D / 32, T / 32, B), tb>>>(v, vT, T, D, (long)T * D, (long)D * T);

        // attn = probs @ v  (Bt = v^T [D,T]; K truncated at bm+128)
        gemm_tt<2, false, false><<<dim3(D / 128, T / 128, B), 256, GEMM_SMEM>>>(
            scores, vT, nullptr, nullptr, nullptr,
            attn, D, T, (long)T * T, (long)D * T, (long)T * D);

        add_ln_kernel<<<BT, 256>>>(x, attn, g1 + (size_t)l * D, beta1 + (size_t)l * D);

        gemm_tt<0, true, true><<<dim3(DF / 128, BT / 128, 1), 256, GEMM_SMEM>>>(
            x, w1T + (size_t)l * DF * D,
            bf1 + (size_t)l * DF, nullptr, nullptr,
            h, DF, D, 0, 0, 0);
        gemm_tt<0, false, true><<<dim3(D / 128, BT / 128, 1), 256, GEMM_SMEM>>>(
            h, w2T + (size_t)l * D * DF,
            bf2 + (size_t)l * D, nullptr, nullptr,
            attn, D, DF, 0, 0, 0);

        add_ln_kernel<<<BT, 256>>>(x, attn, g2 + (size_t)l * D, beta2 + (size_t)l * D);
    }

    gemm_tt<0, false, true><<<dim3(V / 128, BT / 128, 1), 256, GEMM_SMEM>>>(
        x, woutT, bout, nullptr, nullptr,
        out, V, D, 0, 0, 0);
    log_softmax_kernel<<<BT, 256>>>(out);
}

// round 7
// speedup vs baseline: 5.2148x; 1.3690x over previous
#include <cuda_runtime.h>
#include <cuda_fp16.h>
#include <math.h>
#include <stdint.h>

#define B 2
#define T 2048
#define V 32000
#define D 1024
#define DF 4096
#define L 6
#define BT (B*T)

// ---------------- scratch (device globals; no allocation allowed) ----------
__device__ __align__(1024) float  g_x[(size_t)BT * D];
__device__ __align__(1024) __half g_x16[(size_t)BT * D];
__device__ __align__(1024) __half g_qkv16[(size_t)3 * BT * D];
__device__ __align__(1024) __half g_v16T[(size_t)BT * D];
__device__ __align__(1024) float  g_attn[(size_t)BT * D];
__device__ __align__(1024) float  g_scores[(size_t)B * T * T];
__device__ __align__(1024) __half g_probs16[(size_t)B * T * T];
__device__ __align__(1024) __half g_h16[(size_t)BT * DF];
__device__ __align__(1024) __half g_wqkv16[(size_t)L * 3 * D * D];
__device__ __align__(1024) __half g_w1T16[(size_t)L * DF * D];
__device__ __align__(1024) __half g_w2T16[(size_t)L * D * DF];
__device__ __align__(1024) __half g_wout16[(size_t)V * D];

// ---------------- low-level helpers -----------------------------------------
__device__ __forceinline__ uint32_t smem_u32(const void* p) {
    uint32_t a;
    asm("{ .reg .u64 t; cvta.to.shared.u64 t, %1; cvt.u32.u64 %0, t; }" : "=r"(a) : "l"(p));
    return a;
}
__device__ __forceinline__ void cp16(void* smem_dst, const void* gmem_src) {
    uint32_t s = (uint32_t)__cvta_generic_to_shared(smem_dst);
    asm volatile("cp.async.cg.shared.global [%0], [%1], 16;" :: "r"(s), "l"(gmem_src));
}
__device__ __forceinline__ void cp_commit() {
    asm volatile("cp.async.commit_group;" ::: "memory");
}
template<int N>
__device__ __forceinline__ void cp_wait() {
    asm volatile("cp.async.wait_group %0;" :: "n"(N) : "memory");
}
__device__ __forceinline__ void ldsm4(uint32_t addr, uint32_t& r0, uint32_t& r1,
                                      uint32_t& r2, uint32_t& r3) {
    asm volatile("ldmatrix.sync.aligned.m8n8.x4.shared.b16 {%0,%1,%2,%3}, [%4];"
                 : "=r"(r0), "=r"(r1), "=r"(r2), "=r"(r3) : "r"(addr));
}

__device__ __forceinline__ float block_sum(float v, float* red) {
    int tid = threadIdx.x, lane = tid & 31, warp = tid >> 5;
    int nw = blockDim.x >> 5;
    #pragma unroll
    for (int o = 16; o; o >>= 1) v += __shfl_xor_sync(0xffffffffu, v, o);
    if (lane == 0) red[warp] = v;
    __syncthreads();
    float r = (tid < nw) ? red[tid] : 0.0f;
    if (warp == 0) {
        #pragma unroll
        for (int o = 16; o; o >>= 1) r += __shfl_xor_sync(0xffffffffu, r, o);
        if (tid == 0) red[0] = r;
    }
    __syncthreads();
    float out = red[0];
    __syncthreads();
    return out;
}
__device__ __forceinline__ float block_max(float v, float* red) {
    int tid = threadIdx.x, lane = tid & 31, warp = tid >> 5;
    int nw = blockDim.x >> 5;
    #pragma unroll
    for (int o = 16; o; o >>= 1) v = fmaxf(v, __shfl_xor_sync(0xffffffffu, v, o));
    if (lane == 0) red[warp] = v;
    __syncthreads();
    float r = (tid < nw) ? red[tid] : -INFINITY;
    if (warp == 0) {
        #pragma unroll
        for (int o = 16; o; o >>= 1) r = fmaxf(r, __shfl_xor_sync(0xffffffffu, r, o));
        if (tid == 0) red[0] = r;
    }
    __syncthreads();
    float out = red[0];
    __syncthreads();
    return out;
}

// ---------------- embed + positional encoding -------------------------------
__global__ void embed_pe_kernel(const int* __restrict__ tokens,
                                const float* __restrict__ embed,
                                float* __restrict__ x, __half* __restrict__ x16) {
    const int row = blockIdx.x;
    const int t = row % T;
    const int tok = tokens[row];
    const float* erow = embed + (size_t)tok * D;
    float* xrow = x + (size_t)row * D;
    __half* xrow16 = x16 + (size_t)row * D;
    for (int i = threadIdx.x; i < D; i += blockDim.x) {
        int ip = i & ~1;
        double freq = exp(((double)ip / (double)D) * log(10000.0));
        double angle = (double)t / freq;
        float pe = (i & 1) ? (float)cos(angle) : (float)sin(angle);
        float v = erow[i] + pe;
        xrow[i] = v;
        xrow16[i] = __float2half(v);
    }
}

// ---------------- transpose fp32 -> fp16 [R,C] -> [C,R], batched -------------
__global__ void transpose_f2h_kernel(const float* __restrict__ in, __half* __restrict__ out,
                                     int R, int C, long inStride, long outStride) {
    __shared__ float tile[32][33];
    const long zi = blockIdx.z;
    in  += zi * inStride;
    out += zi * outStride;
    const int c0 = blockIdx.x * 32, r0 = blockIdx.y * 32;
    const int tx = threadIdx.x, ty = threadIdx.y;   // 32 x 8
    #pragma unroll
    for (int j = 0; j < 32; j += 8)
        tile[ty + j][tx] = in[(long)(r0 + ty + j) * C + c0 + tx];
    __syncthreads();
    #pragma unroll
    for (int j = 0; j < 32; j += 8)
        out[(long)(c0 + ty + j) * R + r0 + tx] = __float2half(tile[tx][ty + j]);
}

// ---------------- transpose fp16 -> fp16 [R,C] -> [C,R], batched -------------
__global__ void transpose_h2h_kernel(const __half* __restrict__ in, __half* __restrict__ out,
                                     int R, int C, long inStride, long outStride) {
    __shared__ __half tile[32][36];
    const long zi = blockIdx.z;
    in  += zi * inStride;
    out += zi * outStride;
    const int c0 = blockIdx.x * 32, r0 = blockIdx.y * 32;
    const int tx = threadIdx.x, ty = threadIdx.y;   // 32 x 8
    #pragma unroll
    for (int j = 0; j < 32; j += 8)
        tile[ty + j][tx] = in[(long)(r0 + ty + j) * C + c0 + tx];
    __syncthreads();
    #pragma unroll
    for (int j = 0; j < 32; j += 8)
        out[(long)(c0 + ty + j) * R + r0 + tx] = tile[tx][ty + j];
}

// ---------------- FP16 mma.sync TT GEMM --------------------------------------
// C[M,N] = A[M,K] @ Bt[N,K]^T (+bias)(+relu). A,Bt fp16 K-major, fp32 accum.
// 128x128 CTA tile, BK=32 (2x k16), 3-stage cp.async, 8 warps (32x64 per warp).
// CAUSAL: 0 none, 1 skip tiles above diagonal, 2 K truncated at bm+128.
// OUT16: write __half C, else float C.
#define RST 40                                  // halves per smem row (80 B)
#define STAGE_H (256 * RST)                     // halves per stage (A 128 + B 128)
#define GEMM_SMEM16 (3 * STAGE_H * 2)           // 61440 B

template<int CAUSAL, bool RELU, bool BIAS, bool OUT16>
__global__ __launch_bounds__(256, 2) void gemm16(
    const __half* __restrict__ A, const __half* __restrict__ Bt,
    const float* __restrict__ b0, const float* __restrict__ b1, const float* __restrict__ b2,
    void* __restrict__ Cv, int N, int K, long sA, long sB, long sC)
{
    extern __shared__ __half smh[];

    const int bm = blockIdx.y * 128;
    const int bn = blockIdx.x * 128;
    if (CAUSAL == 1 && bn > bm + 127) return;
    const int z = blockIdx.z;
    A  += (long)z * sA;
    Bt += (long)z * sB;

    const int tid = threadIdx.x, warp = tid >> 5, lane = tid & 31;
    const int g = lane >> 2, cg = lane & 3;
    const int wm = (warp >> 1) * 32, wn = (warp & 1) * 64;

    const int Kend = (CAUSAL == 2) ? min(K, bm + 128) : K;
    const int KT = Kend >> 5;

    const uint32_t sbase = smem_u32(smh);

    // ldmatrix.x4 per-lane byte offsets within a stage (canonical m16n8k16 map)
    uint32_t aoff[2], boff[4];
    #pragma unroll
    for (int mi = 0; mi < 2; mi++)
        aoff[mi] = (uint32_t)((wm + mi * 16 + (lane & 15)) * RST * 2 + (lane >> 4) * 16);
    #pragma unroll
    for (int np = 0; np < 4; np++)
        boff[np] = (uint32_t)((128 + wn + np * 16 + (lane & 15)) * RST * 2 + (lane >> 4) * 16);

    auto issue = [&](int s) {
        if (s >= KT) { cp_commit(); return; }
        const int k0 = s << 5;
        __half* As = smh + (s % 3) * STAGE_H;
        __half* Bs = As + 128 * RST;
        #pragma unroll
        for (int i = 0; i < 2; i++) {
            int idx = tid + i * 256;
            int r = idx >> 2, c = (idx & 3) * 8;
            cp16(&As[r * RST + c], A + (long)(bm + r) * K + k0 + c);
            cp16(&Bs[r * RST + c], Bt + (long)(bn + r) * K + k0 + c);
        }
        cp_commit();
    };

    float acc[2][8][4];
    #pragma unroll
    for (int mi = 0; mi < 2; mi++)
        #pragma unroll
        for (int ni = 0; ni < 8; ni++)
            #pragma unroll
            for (int j = 0; j < 4; j++) acc[mi][ni][j] = 0.0f;

    auto comp = [&](int slot) {
        const uint32_t st = sbase + (uint32_t)slot * (STAGE_H * 2);
        #pragma unroll
        for (int ks = 0; ks < 2; ks++) {
            uint32_t af[2][4];
            uint32_t bf[8][2];
            #pragma unroll
            for (int mi = 0; mi < 2; mi++)
                ldsm4(st + aoff[mi] + ks * 32, af[mi][0], af[mi][1], af[mi][2], af[mi][3]);
            #pragma unroll
            for (int np = 0; np < 4; np++) {
                uint32_t q0, q1, q2, q3;
                ldsm4(st + boff[np] + ks * 32, q0, q1, q2, q3);
                bf[2 * np][0] = q0; bf[2 * np][1] = q2;
                bf[2 * np + 1][0] = q1; bf[2 * np + 1][1] = q3;
            }
            #pragma unroll
            for (int mi = 0; mi < 2; mi++)
                #pragma unroll
                for (int ni = 0; ni < 8; ni++)
                    asm volatile(
                        "mma.sync.aligned.m16n8k16.row.col.f32.f16.f16.f32 "
                        "{%0,%1,%2,%3}, {%4,%5,%6,%7}, {%8,%9}, {%0,%1,%2,%3};"
                        : "+f"(acc[mi][ni][0]), "+f"(acc[mi][ni][1]),
                          "+f"(acc[mi][ni][2]), "+f"(acc[mi][ni][3])
                        : "r"(af[mi][0]), "r"(af[mi][1]), "r"(af[mi][2]), "r"(af[mi][3]),
                          "r"(bf[ni][0]), "r"(bf[ni][1]));
        }
    };

    issue(0);
    issue(1);
    for (int i = 0; i < KT; i++) {
        cp_wait<1>();
        __syncthreads();
        issue(i + 2);
        comp(i % 3);
    }

    // epilogue
    const float* bias = BIAS ? (z == 0 ? b0 : (z == 1 ? b1 : b2)) : b0;
    float*  Cf = (float*)Cv  + (long)z * sC;
    __half* Ch = (__half*)Cv + (long)z * sC;
    #pragma unroll
    for (int mi = 0; mi < 2; mi++) {
        const long r0 = bm + wm + mi * 16 + g;
        #pragma unroll
        for (int ni = 0; ni < 8; ni++) {
            const int col = bn + wn + ni * 8 + cg * 2;
            float bb0 = 0.0f, bb1 = 0.0f;
            if (BIAS) { bb0 = bias[col]; bb1 = bias[col + 1]; }
            float2 v0 = make_float2(acc[mi][ni][0] + bb0, acc[mi][ni][1] + bb1);
            float2 v1 = make_float2(acc[mi][ni][2] + bb0, acc[mi][ni][3] + bb1);
            if (RELU) {
                v0.x = fmaxf(v0.x, 0.0f); v0.y = fmaxf(v0.y, 0.0f);
                v1.x = fmaxf(v1.x, 0.0f); v1.y = fmaxf(v1.y, 0.0f);
            }
            if (OUT16) {
                *(__half2*)(Ch + r0 * N + col)       = __floats2half2_rn(v0.x, v0.y);
                *(__half2*)(Ch + (r0 + 8) * N + col) = __floats2half2_rn(v1.x, v1.y);
            } else {
                *(float2*)(Cf + r0 * N + col)       = v0;
                *(float2*)(Cf + (r0 + 8) * N + col) = v1;
            }
        }
    }
}

// ---------------- causal softmax: fp32 scores -> fp16 probs ------------------
__global__ void softmax_causal_kernel(const float* __restrict__ scores,
                                      __half* __restrict__ probs) {
    const int t = blockIdx.x;
    const int b = blockIdx.y;
    const float* row = scores + ((size_t)b * T + t) * T;
    __half* prow = probs + ((size_t)b * T + t) * T;
    const int n = t + 1;
    const float inv_scale = 0.03125f;   // 1/sqrt(1024)
    __shared__ float red[32];
    const int tid = threadIdx.x;

    float m = -INFINITY;
    for (int s = tid; s < n; s += blockDim.x) m = fmaxf(m, row[s] * inv_scale);
    m = block_max(m, red);

    float sum = 0.0f;
    for (int s = tid; s < n; s += blockDim.x) sum += expf(row[s] * inv_scale - m);
    sum = block_sum(sum, red);
    const float inv = 1.0f / sum;

    for (int s = tid; s < n; s += blockDim.x)
        prow[s] = __float2half(expf(row[s] * inv_scale - m) * inv);
    for (int s = n + tid; s < T; s += blockDim.x) prow[s] = __float2half(0.0f);
}

// ---------------- x = LayerNorm(x + y) * g + beta  (fp32 + fp16 out) ---------
__global__ void add_ln_kernel(float* __restrict__ x, __half* __restrict__ x16,
                              const float* __restrict__ y,
                              const float* __restrict__ g, const float* __restrict__ beta) {
    const int row = blockIdx.x;
    __shared__ float buf[D];
    __shared__ float red[32];
    float* xr = x + (size_t)row * D;
    __half* xr16 = x16 + (size_t)row * D;
    const float* yr = y + (size_t)row * D;
    const int tid = threadIdx.x;

    float sum = 0.0f;
    for (int i = tid; i < D; i += blockDim.x) {
        float v = xr[i] + yr[i];
        buf[i] = v;
        sum += v;
    }
    __syncthreads();
    sum = block_sum(sum, red);
    const float mu = sum * (1.0f / D);

    float vs = 0.0f;
    for (int i = tid; i < D; i += blockDim.x) {
        float d = buf[i] - mu;
        vs += d * d;
    }
    vs = block_sum(vs, red);
    const float rstd = rsqrtf(vs * (1.0f / D) + 1e-5f);

    for (int i = tid; i < D; i += blockDim.x) {
        float o = (buf[i] - mu) * rstd * g[i] + beta[i];
        xr[i] = o;
        xr16[i] = __float2half(o);
    }
}

// ---------------- in-place log_softmax over vocab ----------------------------
__global__ void log_softmax_kernel(float* __restrict__ out) {
    float* row = out + (size_t)blockIdx.x * V;
    __shared__ float red[32];
    const int tid = threadIdx.x;

    float m = -INFINITY, s = 0.0f;
    for (int i = tid; i < V; i += blockDim.x) {
        float v = row[i];
        if (v > m) { s = s * expf(m - v) + 1.0f; m = v; }
        else s += expf(v - m);
    }
    float M = block_max(m, red);
    float sum = block_sum(s * expf(m - M), red);
    const float lse = M + logf(sum);

    for (int i = tid; i < V; i += blockDim.x) row[i] -= lse;
}

// ---------------- launch -------------------------------------------------------
extern "C" void kernel_launch(void* const* d_in, const int* in_sizes, int n_in,
                              void* d_out, int out_size) {
    const int*   tokens = (const int*)  d_in[0];
    const float* embed  = (const float*)d_in[1];
    const float* Wq     = (const float*)d_in[2];
    const float* bq     = (const float*)d_in[3];
    const float* Wk     = (const float*)d_in[4];
    const float* bk     = (const float*)d_in[5];
    const float* Wv     = (const float*)d_in[6];
    const float* bv     = (const float*)d_in[7];
    const float* g1     = (const float*)d_in[8];
    const float* beta1  = (const float*)d_in[9];
    const float* W1     = (const float*)d_in[10];
    const float* bf1    = (const float*)d_in[11];
    const float* W2     = (const float*)d_in[12];
    const float* bf2    = (const float*)d_in[13];
    const float* g2     = (const float*)d_in[14];
    const float* beta2  = (const float*)d_in[15];
    const float* Wout   = (const float*)d_in[16];
    const float* bout   = (const float*)d_in[17];
    float* out = (float*)d_out;

    float *x, *attn, *scores;
    __half *x16, *qkv16, *v16T, *probs16, *h16, *wqkv16, *w1T16, *w2T16, *wout16;
    cudaGetSymbolAddress((void**)&x,       g_x);
    cudaGetSymbolAddress((void**)&x16,     g_x16);
    cudaGetSymbolAddress((void**)&qkv16,   g_qkv16);
    cudaGetSymbolAddress((void**)&v16T,    g_v16T);
    cudaGetSymbolAddress((void**)&attn,    g_attn);
    cudaGetSymbolAddress((void**)&scores,  g_scores);
    cudaGetSymbolAddress((void**)&probs16, g_probs16);
    cudaGetSymbolAddress((void**)&h16,     g_h16);
    cudaGetSymbolAddress((void**)&wqkv16,  g_wqkv16);
    cudaGetSymbolAddress((void**)&w1T16,   g_w1T16);
    cudaGetSymbolAddress((void**)&w2T16,   g_w2T16);
    cudaGetSymbolAddress((void**)&wout16,  g_wout16);
    __half* q16 = qkv16;
    __half* k16 = qkv16 + (size_t)BT * D;
    __half* v16 = qkv16 + (size_t)2 * BT * D;

    cudaFuncSetAttribute(gemm16<0, false, true,  true>,  cudaFuncAttributeMaxDynamicSharedMemorySize, GEMM_SMEM16);
    cudaFuncSetAttribute(gemm16<0, true,  true,  true>,  cudaFuncAttributeMaxDynamicSharedMemorySize, GEMM_SMEM16);
    cudaFuncSetAttribute(gemm16<0, false, true,  false>, cudaFuncAttributeMaxDynamicSharedMemorySize, GEMM_SMEM16);
    cudaFuncSetAttribute(gemm16<1, false, false, false>, cudaFuncAttributeMaxDynamicSharedMemorySize, GEMM_SMEM16);
    cudaFuncSetAttribute(gemm16<2, false, false, false>, cudaFuncAttributeMaxDynamicSharedMemorySize, GEMM_SMEM16);

    // ---- weight transposes to [N,K] K-major fp16 ----
    dim3 tb(32, 8);
    transpose_f2h_kernel<<<dim3(D / 32, D / 32, L), tb>>>(Wq, wqkv16 + 0 * (size_t)D * D, D, D, (long)D * D, (long)3 * D * D);
    transpose_f2h_kernel<<<dim3(D / 32, D / 32, L), tb>>>(Wk, wqkv16 + 1 * (size_t)D * D, D, D, (long)D * D, (long)3 * D * D);
    transpose_f2h_kernel<<<dim3(D / 32, D / 32, L), tb>>>(Wv, wqkv16 + 2 * (size_t)D * D, D, D, (long)D * D, (long)3 * D * D);
    transpose_f2h_kernel<<<dim3(DF / 32, D / 32, L), tb>>>(W1, w1T16, D, DF, (long)D * DF, (long)DF * D);
    transpose_f2h_kernel<<<dim3(D / 32, DF / 32, L), tb>>>(W2, w2T16, DF, D, (long)DF * D, (long)D * DF);
    transpose_f2h_kernel<<<dim3(V / 32, D / 32, 1), tb>>>(Wout, wout16, D, V, 0, 0);

    embed_pe_kernel<<<BT, 256>>>(tokens, embed, x, x16);

    for (int l = 0; l < L; ++l) {
        // fused QKV -> fp16 (z = 0,1,2 selects weight slice + bias + out slice)
        gemm16<0, false, true, true><<<dim3(D / 128, BT / 128, 3), 256, GEMM_SMEM16>>>(
            x16, wqkv16 + (size_t)l * 3 * D * D,
            bq + (size_t)l * D, bk + (size_t)l * D, bv + (size_t)l * D,
            qkv16, D, D, 0, (long)D * D, (long)BT * D);

        // scores = q @ k^T per batch -> fp32 (causal tile skip)
        gemm16<1, false, false, false><<<dim3(T / 128, T / 128, B), 256, GEMM_SMEM16>>>(
            q16, k16, nullptr, nullptr, nullptr,
            scores, T, D, (long)T * D, (long)T * D, (long)T * T);

        softmax_causal_kernel<<<dim3(T, B, 1), 256>>>(scores, probs16);

        // v^T per batch: [T,D] -> [D,T] (fp16)
        transpose_h2h_kernel<<<dim3(D / 32, T / 32, B), tb>>>(v16, v16T, T, D, (long)T * D, (long)D * T);

        // attn = probs @ v -> fp32 (K truncated at bm+128)
        gemm16<2, false, false, false><<<dim3(D / 128, T / 128, B), 256, GEMM_SMEM16>>>(
            probs16, v16T, nullptr, nullptr, nullptr,
            attn, D, T, (long)T * T, (long)D * T, (long)T * D);

        add_ln_kernel<<<BT, 256>>>(x, x16, attn, g1 + (size_t)l * D, beta1 + (size_t)l * D);

        // FFN1 -> fp16 h (relu)
        gemm16<0, true, true, true><<<dim3(DF / 128, BT / 128, 1), 256, GEMM_SMEM16>>>(
            x16, w1T16 + (size_t)l * DF * D,
            bf1 + (size_t)l * DF, nullptr, nullptr,
            h16, DF, D, 0, 0, 0);
        // FFN2 -> fp32 attn
        gemm16<0, false, true, false><<<dim3(D / 128, BT / 128, 1), 256, GEMM_SMEM16>>>(
            h16, w2T16 + (size_t)l * D * DF,
            bf2 + (size_t)l * D, nullptr, nullptr,
            attn, D, DF, 0, 0, 0);

        add_ln_kernel<<<BT, 256>>>(x, x16, attn, g2 + (size_t)l * D, beta2 + (size_t)l * D);
    }

    // vocab projection -> fp32 out
    gemm16<0, false, true, false><<<dim3(V / 128, BT / 128, 1), 256, GEMM_SMEM16>>>(
        x16, wout16, bout, nullptr, nullptr,
        out, V, D, 0, 0, 0);
    log_softmax_kernel<<<BT, 256>>>(out);
}